// round 3
// baseline (speedup 1.0000x reference)
#include <cuda_runtime.h>
#include <cuda_bf16.h>
#include <math.h>

// ---------------------------------------------------------------------------
// Problem constants
// ---------------------------------------------------------------------------
#define BATCH 32
#define CCH   128           // channels / d_model
#define HH    110           // spatial
#define PIX   (HH*HH)       // 12100
#define KTOK  768
#define NHEAD 8
#define HD    16
#define NTOK  (BATCH*KTOK)  // 24576
#define KCHUNK 256          // attention split-K chunk
#define NCHUNK (KTOK/KCHUNK)

typedef unsigned long long u64;

// ---------------------------------------------------------------------------
// packed fp32x2 helpers (Blackwell FFMA2 path — only reachable via PTX)
// ---------------------------------------------------------------------------
__device__ __forceinline__ void ffma2(u64 &d, u64 a, u64 b) {
    asm("fma.rn.f32x2 %0, %1, %2, %0;" : "+l"(d) : "l"(a), "l"(b));
}
__device__ __forceinline__ u64 fmul2(u64 a, u64 b) {
    u64 d; asm("mul.rn.f32x2 %0, %1, %2;" : "=l"(d) : "l"(a), "l"(b)); return d;
}
__device__ __forceinline__ u64 fadd2(u64 a, u64 b) {
    u64 d; asm("add.rn.f32x2 %0, %1, %2;" : "=l"(d) : "l"(a), "l"(b)); return d;
}
__device__ __forceinline__ u64 dup2(float x) {
    u64 d; asm("mov.b64 %0, {%1, %1};" : "=l"(d) : "f"(x)); return d;
}
__device__ __forceinline__ u64 pack2(float x, float y) {
    u64 d; asm("mov.b64 %0, {%1, %2};" : "=l"(d) : "f"(x), "f"(y)); return d;
}
__device__ __forceinline__ float2 unpack2(u64 v) {
    float2 r; asm("mov.b64 {%0, %1}, %2;" : "=f"(r.x), "=f"(r.y) : "l"(v)); return r;
}

// ---------------------------------------------------------------------------
// Scratch (static device globals; no allocation allowed)
// ---------------------------------------------------------------------------
__device__ float g_y[4][BATCH*PIX];          // conv partial sums (4 channel chunks)
__device__ float g_imp[BATCH*PIX];           // importance map
__device__ int   g_idx[BATCH*KTOK];          // selected (sorted) pixel indices
__device__ float g_freq[64];                 // positional-encoding frequencies
__device__ float g_tokens[NTOK*CCH];
__device__ float g_qkv[NTOK*3*CCH];
__device__ float g_attn[NTOK*CCH];
__device__ float g_t1[NTOK*CCH];
__device__ float g_h1[NTOK*2*CCH];
__device__ float g_tmp[NTOK*CCH];
__device__ float g_t2[NTOK*CCH];
// attention partials: [b*NHEAD+h][chunk][q][20] = 16 acc + m + l (+2 pad)
__device__ float g_part[BATCH*NHEAD*NCHUNK*KTOK*20];

// ---------------------------------------------------------------------------
// 1) Dilated conv (k=7, d=5, p=15), residue decomposition + f32x2 packing.
// ---------------------------------------------------------------------------
__global__ void conv_kernel(const float* __restrict__ x, const float* __restrict__ w)
{
    __shared__ float tile[62][140];
    __shared__ float ws[49];

    const int cc  = blockIdx.x;
    const int rc  = blockIdx.y;
    const int b   = blockIdx.z;
    const int tid = threadIdx.x;

    const int r_local = tid / 5;
    const int res     = tid % 5;
    const int row0    = rc * 32;
    const int nrows   = min(32, HH - row0);
    const bool active = (r_local < nrows);

    for (int e = tid; e < 62 * 140; e += 160)
        ((float*)tile)[e] = 0.f;

    u64 acc[11];
#pragma unroll
    for (int p = 0; p < 11; p++) acc[p] = 0ull;

    for (int ci = 0; ci < 32; ci++) {
        const int c = cc * 32 + ci;
        __syncthreads();
        if (tid < 49) ws[tid] = w[c * 49 + tid];
        const float* xp = x + ((size_t)b * CCH + c) * PIX;
        for (int e = tid; e < 62 * 110; e += 160) {
            const int tr = e / 110, tc = e % 110;
            const int gr = row0 - 15 + tr;
            tile[tr][15 + tc] = (gr >= 0 && gr < HH) ? xp[gr * HH + tc] : 0.f;
        }
        __syncthreads();

        if (active) {
#pragma unroll
            for (int u = 0; u < 7; u++) {
                const int trow = r_local + 5 * u;
                u64 xp2[27];
                float prev = tile[trow][res];
#pragma unroll
                for (int t = 0; t < 27; t++) {
                    const float cur = tile[trow][res + 5 * (t + 1)];
                    xp2[t] = pack2(prev, cur);
                    prev = cur;
                }
#pragma unroll
                for (int v = 0; v < 7; v++) {
                    const u64 wd = dup2(ws[u * 7 + v]);
#pragma unroll
                    for (int p = 0; p < 11; p++)
                        ffma2(acc[p], wd, xp2[2 * p + v]);
                }
            }
        }
    }

    if (active) {
        const int orow = row0 + r_local;
#pragma unroll
        for (int p = 0; p < 11; p++) {
            const float2 t = unpack2(acc[p]);
            g_y[cc][b * PIX + orow * HH + res + 5 * (2 * p)]     = t.x;
            g_y[cc][b * PIX + orow * HH + res + 5 * (2 * p + 1)] = t.y;
        }
    }
}

// ---------------------------------------------------------------------------
// 2) importance = sigmoid(gelu(BN(conv + bias)))
// ---------------------------------------------------------------------------
__global__ void imp_kernel(const float* __restrict__ cb, const float* __restrict__ bg,
                           const float* __restrict__ bb, const float* __restrict__ bm,
                           const float* __restrict__ bv)
{
    const int i = blockIdx.x * 256 + threadIdx.x;
    if (i >= BATCH * PIX) return;
    float y = g_y[0][i] + g_y[1][i] + g_y[2][i] + g_y[3][i] + cb[0];
    const float scale = bg[0] * rsqrtf(bv[0] + 1e-5f);
    y = (y - bm[0]) * scale + bb[0];
    const float g = 0.5f * y * (1.f + erff(y * 0.70710678118654752f));
    g_imp[i] = 1.f / (1.f + expf(-g));
}

// ---------------------------------------------------------------------------
// 3) top-K per batch. All bits cached in dynamic smem. 4-round radix-256
//    threshold, then warp-per-chunk ballot compaction (2 block syncs only).
//    Ties: lowest index first; output ascending.
// ---------------------------------------------------------------------------
#define NCHK ((PIX + 255) / 256)   // 48

__global__ void topk_kernel()
{
    extern __shared__ unsigned sbits[];     // [PIX]
    __shared__ int hist[256];
    __shared__ int cgt[NCHK], ceq[NCHK];
    __shared__ unsigned sh_prefix;
    __shared__ int sh_above;

    const int b    = blockIdx.x;
    const int tid  = threadIdx.x;
    const int lane = tid & 31;
    const int wrp  = tid >> 5;
    const float* v = g_imp + b * PIX;

    for (int i = tid; i < PIX; i += 256)
        sbits[i] = __float_as_uint(v[i]);
    __syncthreads();

    unsigned prefix = 0;
    int kneed = KTOK;

#pragma unroll
    for (int shift = 24; shift >= 0; shift -= 8) {
        hist[tid] = 0;
        __syncthreads();
        const unsigned pm = (shift == 24) ? 0u : (0xFFFFFFFFu << (shift + 8));
        for (int i = tid; i < PIX; i += 256) {
            const unsigned bits = sbits[i];
            if ((bits & pm) == prefix)
                atomicAdd(&hist[(bits >> shift) & 255], 1);
        }
        __syncthreads();
        for (int off = 1; off < 256; off <<= 1) {
            const int val = (tid + off < 256) ? hist[tid + off] : 0;
            __syncthreads();
            hist[tid] += val;
            __syncthreads();
        }
        const int here  = hist[tid];
        const int above = (tid == 255) ? 0 : hist[tid + 1];
        if (here >= kneed && above < kneed) {
            sh_prefix = prefix | ((unsigned)tid << shift);
            sh_above  = above;
        }
        __syncthreads();
        prefix = sh_prefix;
        kneed -= sh_above;
        __syncthreads();
    }

    const unsigned T = prefix;
    const int tn = kneed;              // ties to take (lowest index first)

    // per-chunk gt/eq counts (warp w handles chunks w, w+8, ...)
    for (int c = wrp; c < NCHK; c += 8) {
        int gt = 0, eq = 0;
#pragma unroll
        for (int g = 0; g < 8; g++) {
            const int i = c * 256 + g * 32 + lane;
            const unsigned bits = (i < PIX) ? sbits[i] : 0u;
            const unsigned bg = __ballot_sync(0xffffffffu, bits > T);
            const unsigned be = __ballot_sync(0xffffffffu, bits == T && i < PIX);
            gt += __popc(bg); eq += __popc(be);
        }
        if (lane == 0) { cgt[c] = gt; ceq[c] = eq; }
    }
    __syncthreads();
    if (tid == 0) {
        int sg = 0, se = 0;
        for (int c = 0; c < NCHK; c++) {
            const int tg = cgt[c], te = ceq[c];
            cgt[c] = sg; ceq[c] = se;
            sg += tg; se += te;
        }
    }
    __syncthreads();

    // write phase: ordered compaction per chunk
    const unsigned lmask = (1u << lane) - 1u;
    for (int c = wrp; c < NCHK; c += 8) {
        int gt_run = cgt[c], eq_run = ceq[c];
#pragma unroll
        for (int g = 0; g < 8; g++) {
            const int i = c * 256 + g * 32 + lane;
            const unsigned bits = (i < PIX) ? sbits[i] : 0u;
            const bool isgt = bits > T;
            const bool iseq = (bits == T) && (i < PIX);
            const unsigned bg = __ballot_sync(0xffffffffu, isgt);
            const unsigned be = __ballot_sync(0xffffffffu, iseq);
            const int gt_before = gt_run + __popc(bg & lmask);
            const int eq_before = eq_run + __popc(be & lmask);
            if (isgt)
                g_idx[b * KTOK + gt_before + min(eq_before, tn)] = i;
            else if (iseq && eq_before < tn)
                g_idx[b * KTOK + gt_before + eq_before] = i;
            gt_run += __popc(bg);
            eq_run += __popc(be);
        }
    }
}

// ---------------------------------------------------------------------------
// 4) positional-encoding frequency table
// ---------------------------------------------------------------------------
__global__ void freq_kernel()
{
    const int i = threadIdx.x;           // 64
    const float cst = (float)(-(log(10000.0) / 128.0));
    const float a = (float)(2 * i) * cst;
    g_freq[i] = (float)exp((double)a);
}

// ---------------------------------------------------------------------------
// 5) gather tokens: tokens[b,k,c] = x[b,c,p]*imp[b,p] + PE[p,c]
// ---------------------------------------------------------------------------
__global__ void gather_kernel(const float* __restrict__ x)
{
    const int b = blockIdx.y, k = blockIdx.x, c = threadIdx.x;
    const int p = g_idx[b * KTOK + k];
    const float val = x[((size_t)b * CCH + c) * PIX + p] * g_imp[b * PIX + p];
    const float arg = (float)p * g_freq[c >> 1];
    const float pe  = (c & 1) ? cosf(arg) : sinf(arg);
    g_tokens[((size_t)b * KTOK + k) * CCH + c] = val + pe;
}

// ---------------------------------------------------------------------------
// 6) tiled SGEMM with FFMA2: C[m,n] = act( sum_k A[m,k]*B[n,k] + bias[n] )
// ---------------------------------------------------------------------------
template <bool RELU>
__global__ __launch_bounds__(256) void gemm_abt(
    const float* __restrict__ A, const float* __restrict__ B,
    const float* __restrict__ bias, float* __restrict__ C,
    int M, int N, int K)
{
    __shared__ float As[16][132];
    __shared__ float Bs[16][132];

    const int tid = threadIdx.x;
    const int bm = blockIdx.y * 128, bn = blockIdx.x * 128;
    const int tx = tid & 15, ty = tid >> 4;

    u64 acc[8][4];
#pragma unroll
    for (int i = 0; i < 8; i++)
#pragma unroll
        for (int j = 0; j < 4; j++) acc[i][j] = 0ull;

    for (int k0 = 0; k0 < K; k0 += 16) {
#pragma unroll
        for (int i = 0; i < 2; i++) {
            const int f  = tid + i * 256;
            const int m  = f >> 2;
            const int kk = (f & 3) * 4;
            const float4 a4 = *(const float4*)&A[(size_t)(bm + m) * K + k0 + kk];
            const float4 b4 = *(const float4*)&B[(size_t)(bn + m) * K + k0 + kk];
            As[kk + 0][m] = a4.x; As[kk + 1][m] = a4.y;
            As[kk + 2][m] = a4.z; As[kk + 3][m] = a4.w;
            Bs[kk + 0][m] = b4.x; Bs[kk + 1][m] = b4.y;
            Bs[kk + 2][m] = b4.z; Bs[kk + 3][m] = b4.w;
        }
        __syncthreads();
#pragma unroll
        for (int kk = 0; kk < 16; kk++) {
            const float4 a0 = *(const float4*)&As[kk][ty * 8];
            const float4 a1 = *(const float4*)&As[kk][ty * 8 + 4];
            const ulonglong2 bl0 = *(const ulonglong2*)&Bs[kk][tx * 8];
            const ulonglong2 bl1 = *(const ulonglong2*)&Bs[kk][tx * 8 + 4];
            const u64 bb[4] = { bl0.x, bl0.y, bl1.x, bl1.y };
            const u64 ad[8] = { dup2(a0.x), dup2(a0.y), dup2(a0.z), dup2(a0.w),
                                dup2(a1.x), dup2(a1.y), dup2(a1.z), dup2(a1.w) };
#pragma unroll
            for (int i = 0; i < 8; i++)
#pragma unroll
                for (int j = 0; j < 4; j++)
                    ffma2(acc[i][j], ad[i], bb[j]);
        }
        __syncthreads();
    }

    const u64* bp = (const u64*)&bias[bn + tx * 8];
    const u64 bb[4] = { bp[0], bp[1], bp[2], bp[3] };
#pragma unroll
    for (int i = 0; i < 8; i++) {
        u64 r[4];
#pragma unroll
        for (int j = 0; j < 4; j++) {
            r[j] = fadd2(acc[i][j], bb[j]);
            if (RELU) {
                float2 t = unpack2(r[j]);
                t.x = fmaxf(t.x, 0.f); t.y = fmaxf(t.y, 0.f);
                r[j] = pack2(t.x, t.y);
            }
        }
        float* crow = &C[(size_t)(bm + ty * 8 + i) * N + bn + tx * 8];
        *(ulonglong2*)(crow)     = make_ulonglong2(r[0], r[1]);
        *(ulonglong2*)(crow + 4) = make_ulonglong2(r[2], r[3]);
    }
}

// ---------------------------------------------------------------------------
// 7) attention, split-K: block = (head, batch, key-chunk of 256).
//    Each block computes partial online softmax (m, l, unnormalized acc[16])
//    for all 768 queries over its 256 keys. Combine kernel merges chunks.
// ---------------------------------------------------------------------------
__global__ void attn_part_kernel()
{
    extern __shared__ u64 sm2[];
    u64* Ks = sm2;                     // [256][8] packed pairs
    u64* Vs = sm2 + KCHUNK * 8;

    const int h = blockIdx.x, b = blockIdx.y, c = blockIdx.z;
    const int tid = threadIdx.x;
    const float* qkv = g_qkv + (size_t)b * KTOK * 3 * CCH;
    const int jbase = c * KCHUNK;

    for (int e = tid; e < KCHUNK * 8; e += 256) {
        const int j = jbase + (e >> 3), d2 = e & 7;
        Ks[e] = *(const u64*)&qkv[(size_t)j * 384 + 128 + h * HD + d2 * 2];
        Vs[e] = *(const u64*)&qkv[(size_t)j * 384 + 256 + h * HD + d2 * 2];
    }
    __syncthreads();

    for (int qi = 0; qi < 3; qi++) {
        const int q = qi * 256 + tid;
        const u64* qp = (const u64*)(qkv + (size_t)q * 384 + h * HD);
        const u64 sc = dup2(0.25f);    // 1/sqrt(16)
        u64 qv[8];
#pragma unroll
        for (int d = 0; d < 8; d++) qv[d] = fmul2(qp[d], sc);

        float m = -1e30f, l = 0.f;
        u64 a[8];
#pragma unroll
        for (int d = 0; d < 8; d++) a[d] = 0ull;

        for (int j0 = 0; j0 < KCHUNK; j0 += 8) {
            float s[8];
#pragma unroll
            for (int jj = 0; jj < 8; jj++) {
                const ulonglong2* kp = (const ulonglong2*)&Ks[(size_t)(j0 + jj) * 8];
                const ulonglong2 k0 = kp[0], k1 = kp[1], k2 = kp[2], k3 = kp[3];
                u64 d2 = fmul2(qv[0], k0.x);
                ffma2(d2, qv[1], k0.y);
                ffma2(d2, qv[2], k1.x);
                ffma2(d2, qv[3], k1.y);
                ffma2(d2, qv[4], k2.x);
                ffma2(d2, qv[5], k2.y);
                ffma2(d2, qv[6], k3.x);
                ffma2(d2, qv[7], k3.y);
                const float2 t = unpack2(d2);
                s[jj] = t.x + t.y;
            }
            float cm = s[0];
#pragma unroll
            for (int jj = 1; jj < 8; jj++) cm = fmaxf(cm, s[jj]);
            const float nm = fmaxf(m, cm);
            const float scale = __expf(m - nm);
            const u64 sc2 = dup2(scale);
            l *= scale;
#pragma unroll
            for (int d = 0; d < 8; d++) a[d] = fmul2(a[d], sc2);
            m = nm;
#pragma unroll
            for (int jj = 0; jj < 8; jj++) {
                const float e = __expf(s[jj] - m);
                l += e;
                const u64 e2 = dup2(e);
                const ulonglong2* vp = (const ulonglong2*)&Vs[(size_t)(j0 + jj) * 8];
                const ulonglong2 v0 = vp[0], v1 = vp[1], v2 = vp[2], v3 = vp[3];
                ffma2(a[0], e2, v0.x);
                ffma2(a[1], e2, v0.y);
                ffma2(a[2], e2, v1.x);
                ffma2(a[3], e2, v1.y);
                ffma2(a[4], e2, v2.x);
                ffma2(a[5], e2, v2.y);
                ffma2(a[6], e2, v3.x);
                ffma2(a[7], e2, v3.y);
            }
        }
        float* pp = g_part + ((((size_t)(b * NHEAD + h) * NCHUNK + c) * KTOK + q) * 20);
#pragma unroll
        for (int d = 0; d < 4; d++)
            *(ulonglong2*)(pp + d * 4) = make_ulonglong2(a[2 * d], a[2 * d + 1]);
        pp[16] = m;
        pp[17] = l;
    }
}

__global__ void attn_combine_kernel()
{
    const int id = blockIdx.x * 256 + threadIdx.x;     // < BATCH*NHEAD*KTOK
    const int bh = id / KTOK;
    const int q  = id - bh * KTOK;
    const int b  = bh / NHEAD, h = bh - b * NHEAD;

    const float* p0 = g_part + (((size_t)bh * NCHUNK + 0) * KTOK + q) * 20;
    const float* p1 = p0 + (size_t)KTOK * 20;
    const float* p2 = p1 + (size_t)KTOK * 20;

    const float m0 = p0[16], m1 = p1[16], m2 = p2[16];
    const float M  = fmaxf(m0, fmaxf(m1, m2));
    const float w0 = __expf(m0 - M), w1 = __expf(m1 - M), w2 = __expf(m2 - M);
    const float L  = w0 * p0[17] + w1 * p1[17] + w2 * p2[17];
    const float inv = 1.f / L;

    float* orow = g_attn + ((size_t)b * KTOK + q) * CCH + h * HD;
#pragma unroll
    for (int d = 0; d < 16; d++)
        orow[d] = (w0 * p0[d] + w1 * p1[d] + w2 * p2[d]) * inv;
}

// ---------------------------------------------------------------------------
// 8) residual + LayerNorm
// ---------------------------------------------------------------------------
__global__ void ln_kernel(const float* __restrict__ a, const float* __restrict__ r,
                          const float* __restrict__ g, const float* __restrict__ be,
                          float* __restrict__ out)
{
    const int row  = blockIdx.x * 8 + (threadIdx.x >> 5);
    const int lane = threadIdx.x & 31;
    const float4 va = ((const float4*)(a + (size_t)row * CCH))[lane];
    const float4 vr = ((const float4*)(r + (size_t)row * CCH))[lane];
    float4 t;
    t.x = va.x + vr.x; t.y = va.y + vr.y; t.z = va.z + vr.z; t.w = va.w + vr.w;
    float s  = t.x + t.y + t.z + t.w;
    float s2 = t.x*t.x + t.y*t.y + t.z*t.z + t.w*t.w;
#pragma unroll
    for (int o = 16; o > 0; o >>= 1) {
        s  += __shfl_xor_sync(0xffffffffu, s,  o);
        s2 += __shfl_xor_sync(0xffffffffu, s2, o);
    }
    const float mu  = s * (1.f / 128.f);
    const float var = s2 * (1.f / 128.f) - mu * mu;
    const float inv = rsqrtf(var + 1e-5f);
    const float4 gv = ((const float4*)g)[lane];
    const float4 bv = ((const float4*)be)[lane];
    float4 o;
    o.x = (t.x - mu) * inv * gv.x + bv.x;
    o.y = (t.y - mu) * inv * gv.y + bv.y;
    o.z = (t.z - mu) * inv * gv.z + bv.z;
    o.w = (t.w - mu) * inv * gv.w + bv.w;
    ((float4*)(out + (size_t)row * CCH))[lane] = o;
}

// ---------------------------------------------------------------------------
// 9) out = x * imp (everywhere), then scatter t2 at selected pixels
// ---------------------------------------------------------------------------
__global__ void xs_kernel(const float* __restrict__ x, float* __restrict__ out)
{
    const unsigned i = blockIdx.x * 256u + threadIdx.x;
    const unsigned total = (unsigned)BATCH * CCH * (PIX / 4);
    if (i >= total) return;
    const unsigned base = i * 4u;
    const unsigned p4 = base % PIX;
    const unsigned b  = (base / PIX) / CCH;
    const float4 xv = *(const float4*)(x + base);
    const float* ip = g_imp + (size_t)b * PIX + p4;
    float4 o;
    o.x = xv.x * ip[0]; o.y = xv.y * ip[1]; o.z = xv.z * ip[2]; o.w = xv.w * ip[3];
    *(float4*)(out + base) = o;
}

__global__ void scatter_kernel(float* __restrict__ out)
{
    const int b = blockIdx.y, k = blockIdx.x, c = threadIdx.x;
    const int p = g_idx[b * KTOK + k];
    out[((size_t)b * CCH + c) * PIX + p] = g_t2[((size_t)b * KTOK + k) * CCH + c];
}

// ---------------------------------------------------------------------------
// launch
// ---------------------------------------------------------------------------
extern "C" void kernel_launch(void* const* d_in, const int* in_sizes, int n_in,
                              void* d_out, int out_size)
{
    const float* x      = (const float*)d_in[0];
    const float* conv_w = (const float*)d_in[1];
    const float* conv_b = (const float*)d_in[2];
    const float* bn_g   = (const float*)d_in[3];
    const float* bn_b   = (const float*)d_in[4];
    const float* bn_m   = (const float*)d_in[5];
    const float* bn_v   = (const float*)d_in[6];
    const float* w_qkv  = (const float*)d_in[7];
    const float* b_qkv  = (const float*)d_in[8];
    const float* w_o    = (const float*)d_in[9];
    const float* b_o    = (const float*)d_in[10];
    const float* ln1_g  = (const float*)d_in[11];
    const float* ln1_b  = (const float*)d_in[12];
    const float* w1     = (const float*)d_in[13];
    const float* b1     = (const float*)d_in[14];
    const float* w2     = (const float*)d_in[15];
    const float* b2     = (const float*)d_in[16];
    const float* ln2_g  = (const float*)d_in[17];
    const float* ln2_b  = (const float*)d_in[18];
    float* out = (float*)d_out;

    float *p_tokens, *p_qkv, *p_attn, *p_t1, *p_h1, *p_tmp, *p_t2;
    cudaGetSymbolAddress((void**)&p_tokens, g_tokens);
    cudaGetSymbolAddress((void**)&p_qkv,    g_qkv);
    cudaGetSymbolAddress((void**)&p_attn,   g_attn);
    cudaGetSymbolAddress((void**)&p_t1,     g_t1);
    cudaGetSymbolAddress((void**)&p_h1,     g_h1);
    cudaGetSymbolAddress((void**)&p_tmp,    g_tmp);
    cudaGetSymbolAddress((void**)&p_t2,     g_t2);

    cudaFuncSetAttribute(topk_kernel, cudaFuncAttributeMaxDynamicSharedMemorySize,
                         PIX * (int)sizeof(unsigned));
    cudaFuncSetAttribute(attn_part_kernel, cudaFuncAttributeMaxDynamicSharedMemorySize,
                         2 * KCHUNK * HD * (int)sizeof(float));

    // conv -> importance -> top-K -> tokens
    freq_kernel<<<1, 64>>>();
    conv_kernel<<<dim3(4, 4, BATCH), 160>>>(x, conv_w);
    imp_kernel<<<(BATCH * PIX + 255) / 256, 256>>>(conv_b, bn_g, bn_b, bn_m, bn_v);
    topk_kernel<<<BATCH, 256, PIX * sizeof(unsigned)>>>();
    gather_kernel<<<dim3(KTOK, BATCH), CCH>>>(x);

    // transformer encoder layer
    gemm_abt<false><<<dim3(384 / 128, NTOK / 128), 256>>>(p_tokens, w_qkv, b_qkv, p_qkv, NTOK, 384, 128);

    attn_part_kernel<<<dim3(NHEAD, BATCH, NCHUNK), 256, 2 * KCHUNK * HD * sizeof(float)>>>();
    attn_combine_kernel<<<(BATCH * NHEAD * KTOK) / 256, 256>>>();

    gemm_abt<false><<<dim3(128 / 128, NTOK / 128), 256>>>(p_attn, w_o, b_o, p_tmp, NTOK, 128, 128);
    ln_kernel<<<NTOK / 8, 256>>>(p_tokens, p_tmp, ln1_g, ln1_b, p_t1);
    gemm_abt<true ><<<dim3(256 / 128, NTOK / 128), 256>>>(p_t1, w1, b1, p_h1, NTOK, 256, 128);
    gemm_abt<false><<<dim3(128 / 128, NTOK / 128), 256>>>(p_h1, w2, b2, p_tmp, NTOK, 128, 256);
    ln_kernel<<<NTOK / 8, 256>>>(p_t1, p_tmp, ln2_g, ln2_b, p_t2);

    // assemble output
    xs_kernel<<<(BATCH * CCH * (PIX / 4) + 255) / 256, 256>>>(x, out);
    scatter_kernel<<<dim3(KTOK, BATCH), CCH>>>(out);
}

// round 4
// speedup vs baseline: 1.1303x; 1.1303x over previous
#include <cuda_runtime.h>
#include <cuda_bf16.h>
#include <math.h>

// ---------------------------------------------------------------------------
// Problem constants
// ---------------------------------------------------------------------------
#define BATCH 32
#define CCH   128           // channels / d_model
#define HH    110           // spatial
#define PIX   (HH*HH)       // 12100
#define KTOK  768
#define NHEAD 8
#define HD    16
#define NTOK  (BATCH*KTOK)  // 24576

typedef unsigned long long u64;

// ---------------------------------------------------------------------------
// packed fp32x2 helpers (Blackwell FFMA2 path — only reachable via PTX)
// ---------------------------------------------------------------------------
__device__ __forceinline__ void ffma2(u64 &d, u64 a, u64 b) {
    asm("fma.rn.f32x2 %0, %1, %2, %0;" : "+l"(d) : "l"(a), "l"(b));
}
__device__ __forceinline__ u64 fmul2(u64 a, u64 b) {
    u64 d; asm("mul.rn.f32x2 %0, %1, %2;" : "=l"(d) : "l"(a), "l"(b)); return d;
}
__device__ __forceinline__ u64 dup2(float x) {
    u64 d; asm("mov.b64 %0, {%1, %1};" : "=l"(d) : "f"(x)); return d;
}
__device__ __forceinline__ u64 pack2(float x, float y) {
    u64 d; asm("mov.b64 %0, {%1, %2};" : "=l"(d) : "f"(x), "f"(y)); return d;
}
__device__ __forceinline__ float2 unpack2(u64 v) {
    float2 r; asm("mov.b64 {%0, %1}, %2;" : "=f"(r.x), "=f"(r.y) : "l"(v)); return r;
}
__device__ __forceinline__ unsigned tf32_of(float x) {
    unsigned r; asm("cvt.rna.tf32.f32 %0, %1;" : "=r"(r) : "f"(x)); return r;
}

// ---------------------------------------------------------------------------
// Scratch (static device globals; no allocation allowed)
// ---------------------------------------------------------------------------
__device__ float g_y[4][BATCH*PIX];          // conv partial sums (4 channel chunks)
__device__ float g_imp[BATCH*PIX];           // importance map
__device__ int   g_idx[BATCH*KTOK];          // selected (sorted) pixel indices
__device__ float g_freq[64];                 // positional-encoding frequencies
__device__ float g_tokens[NTOK*CCH];
__device__ float g_qkv[NTOK*3*CCH];
__device__ float g_attn[NTOK*CCH];
__device__ float g_t1[NTOK*CCH];
__device__ float g_h1[NTOK*2*CCH];
__device__ float g_tmp[NTOK*CCH];
__device__ float g_t2[NTOK*CCH];

// ---------------------------------------------------------------------------
// 1) Dilated conv (k=7, d=5, p=15), residue decomposition + f32x2 packing.
// ---------------------------------------------------------------------------
__global__ void conv_kernel(const float* __restrict__ x, const float* __restrict__ w)
{
    __shared__ float tile[62][140];
    __shared__ float ws[49];

    const int cc  = blockIdx.x;
    const int rc  = blockIdx.y;
    const int b   = blockIdx.z;
    const int tid = threadIdx.x;

    const int r_local = tid / 5;
    const int res     = tid % 5;
    const int row0    = rc * 32;
    const int nrows   = min(32, HH - row0);
    const bool active = (r_local < nrows);

    for (int e = tid; e < 62 * 140; e += 160)
        ((float*)tile)[e] = 0.f;

    u64 acc[11];
#pragma unroll
    for (int p = 0; p < 11; p++) acc[p] = 0ull;

    for (int ci = 0; ci < 32; ci++) {
        const int c = cc * 32 + ci;
        __syncthreads();
        if (tid < 49) ws[tid] = w[c * 49 + tid];
        const float* xp = x + ((size_t)b * CCH + c) * PIX;
        for (int e = tid; e < 62 * 110; e += 160) {
            const int tr = e / 110, tc = e % 110;
            const int gr = row0 - 15 + tr;
            tile[tr][15 + tc] = (gr >= 0 && gr < HH) ? xp[gr * HH + tc] : 0.f;
        }
        __syncthreads();

        if (active) {
#pragma unroll
            for (int u = 0; u < 7; u++) {
                const int trow = r_local + 5 * u;
                u64 xp2[27];
                float prev = tile[trow][res];
#pragma unroll
                for (int t = 0; t < 27; t++) {
                    const float cur = tile[trow][res + 5 * (t + 1)];
                    xp2[t] = pack2(prev, cur);
                    prev = cur;
                }
#pragma unroll
                for (int v = 0; v < 7; v++) {
                    const u64 wd = dup2(ws[u * 7 + v]);
#pragma unroll
                    for (int p = 0; p < 11; p++)
                        ffma2(acc[p], wd, xp2[2 * p + v]);
                }
            }
        }
    }

    if (active) {
        const int orow = row0 + r_local;
#pragma unroll
        for (int p = 0; p < 11; p++) {
            const float2 t = unpack2(acc[p]);
            g_y[cc][b * PIX + orow * HH + res + 5 * (2 * p)]     = t.x;
            g_y[cc][b * PIX + orow * HH + res + 5 * (2 * p + 1)] = t.y;
        }
    }
}

// ---------------------------------------------------------------------------
// 2) importance = sigmoid(gelu(BN(conv + bias)))
// ---------------------------------------------------------------------------
__global__ void imp_kernel(const float* __restrict__ cb, const float* __restrict__ bg,
                           const float* __restrict__ bb, const float* __restrict__ bm,
                           const float* __restrict__ bv)
{
    const int i = blockIdx.x * 256 + threadIdx.x;
    if (i >= BATCH * PIX) return;
    float y = g_y[0][i] + g_y[1][i] + g_y[2][i] + g_y[3][i] + cb[0];
    const float scale = bg[0] * rsqrtf(bv[0] + 1e-5f);
    y = (y - bm[0]) * scale + bb[0];
    const float g = 0.5f * y * (1.f + erff(y * 0.70710678118654752f));
    g_imp[i] = 1.f / (1.f + expf(-g));
}

// ---------------------------------------------------------------------------
// 3) top-K per batch (unchanged from R3)
// ---------------------------------------------------------------------------
#define NCHK ((PIX + 255) / 256)   // 48

__global__ void topk_kernel()
{
    extern __shared__ unsigned sbits[];     // [PIX]
    __shared__ int hist[256];
    __shared__ int cgt[NCHK], ceq[NCHK];
    __shared__ unsigned sh_prefix;
    __shared__ int sh_above;

    const int b    = blockIdx.x;
    const int tid  = threadIdx.x;
    const int lane = tid & 31;
    const int wrp  = tid >> 5;
    const float* v = g_imp + b * PIX;

    for (int i = tid; i < PIX; i += 256)
        sbits[i] = __float_as_uint(v[i]);
    __syncthreads();

    unsigned prefix = 0;
    int kneed = KTOK;

#pragma unroll
    for (int shift = 24; shift >= 0; shift -= 8) {
        hist[tid] = 0;
        __syncthreads();
        const unsigned pm = (shift == 24) ? 0u : (0xFFFFFFFFu << (shift + 8));
        for (int i = tid; i < PIX; i += 256) {
            const unsigned bits = sbits[i];
            if ((bits & pm) == prefix)
                atomicAdd(&hist[(bits >> shift) & 255], 1);
        }
        __syncthreads();
        for (int off = 1; off < 256; off <<= 1) {
            const int val = (tid + off < 256) ? hist[tid + off] : 0;
            __syncthreads();
            hist[tid] += val;
            __syncthreads();
        }
        const int here  = hist[tid];
        const int above = (tid == 255) ? 0 : hist[tid + 1];
        if (here >= kneed && above < kneed) {
            sh_prefix = prefix | ((unsigned)tid << shift);
            sh_above  = above;
        }
        __syncthreads();
        prefix = sh_prefix;
        kneed -= sh_above;
        __syncthreads();
    }

    const unsigned T = prefix;
    const int tn = kneed;

    for (int c = wrp; c < NCHK; c += 8) {
        int gt = 0, eq = 0;
#pragma unroll
        for (int g = 0; g < 8; g++) {
            const int i = c * 256 + g * 32 + lane;
            const unsigned bits = (i < PIX) ? sbits[i] : 0u;
            const unsigned bg = __ballot_sync(0xffffffffu, bits > T);
            const unsigned be = __ballot_sync(0xffffffffu, bits == T && i < PIX);
            gt += __popc(bg); eq += __popc(be);
        }
        if (lane == 0) { cgt[c] = gt; ceq[c] = eq; }
    }
    __syncthreads();
    if (tid == 0) {
        int sg = 0, se = 0;
        for (int c = 0; c < NCHK; c++) {
            const int tg = cgt[c], te = ceq[c];
            cgt[c] = sg; ceq[c] = se;
            sg += tg; se += te;
        }
    }
    __syncthreads();

    const unsigned lmask = (1u << lane) - 1u;
    for (int c = wrp; c < NCHK; c += 8) {
        int gt_run = cgt[c], eq_run = ceq[c];
#pragma unroll
        for (int g = 0; g < 8; g++) {
            const int i = c * 256 + g * 32 + lane;
            const unsigned bits = (i < PIX) ? sbits[i] : 0u;
            const bool isgt = bits > T;
            const bool iseq = (bits == T) && (i < PIX);
            const unsigned bg = __ballot_sync(0xffffffffu, isgt);
            const unsigned be = __ballot_sync(0xffffffffu, iseq);
            const int gt_before = gt_run + __popc(bg & lmask);
            const int eq_before = eq_run + __popc(be & lmask);
            if (isgt)
                g_idx[b * KTOK + gt_before + min(eq_before, tn)] = i;
            else if (iseq && eq_before < tn)
                g_idx[b * KTOK + gt_before + eq_before] = i;
            gt_run += __popc(bg);
            eq_run += __popc(be);
        }
    }
}

// ---------------------------------------------------------------------------
// 4) positional-encoding frequency table
// ---------------------------------------------------------------------------
__global__ void freq_kernel()
{
    const int i = threadIdx.x;           // 64
    const float cst = (float)(-(log(10000.0) / 128.0));
    const float a = (float)(2 * i) * cst;
    g_freq[i] = (float)exp((double)a);
}

// ---------------------------------------------------------------------------
// 5) gather tokens: tokens[b,k,c] = x[b,c,p]*imp[b,p] + PE[p,c]
// ---------------------------------------------------------------------------
__global__ void gather_kernel(const float* __restrict__ x)
{
    const int b = blockIdx.y, k = blockIdx.x, c = threadIdx.x;
    const int p = g_idx[b * KTOK + k];
    const float val = x[((size_t)b * CCH + c) * PIX + p] * g_imp[b * PIX + p];
    const float arg = (float)p * g_freq[c >> 1];
    const float pe  = (c & 1) ? cosf(arg) : sinf(arg);
    g_tokens[((size_t)b * KTOK + k) * CCH + c] = val + pe;
}

// ---------------------------------------------------------------------------
// 6) tf32 tensor-core GEMM: C[m,n] = act( sum_k A[m,k]*B[n,k] + bias[n] )
//    BM=128, BN=64, BK=32, 256 threads (8 warps as 4x2), warp tile 32x32,
//    mma.sync.m16n8k8 tf32, fp32 accumulate.
// ---------------------------------------------------------------------------
template <bool RELU>
__global__ __launch_bounds__(256) void gemm_tf32(
    const float* __restrict__ A, const float* __restrict__ B,
    const float* __restrict__ bias, float* __restrict__ C,
    int M, int N, int K)
{
    __shared__ unsigned As[128][33];
    __shared__ unsigned Bs[64][33];

    const int tid  = threadIdx.x;
    const int lane = tid & 31;
    const int wid  = tid >> 5;
    const int wm   = wid >> 1;        // 0..3
    const int wn   = wid & 1;         // 0..1
    const int g    = lane >> 2;       // group 0..7
    const int tg   = lane & 3;        // 0..3
    const int bm   = blockIdx.y * 128, bn = blockIdx.x * 64;

    float acc[2][4][4];
#pragma unroll
    for (int mi = 0; mi < 2; mi++)
#pragma unroll
        for (int ni = 0; ni < 4; ni++)
#pragma unroll
            for (int e = 0; e < 4; e++) acc[mi][ni][e] = 0.f;

    for (int k0 = 0; k0 < K; k0 += 32) {
#pragma unroll
        for (int i = 0; i < 4; i++) {
            const int f = tid + i * 256;
            const int row = f >> 3, c4 = (f & 7) * 4;
            const float4 v = *(const float4*)&A[(size_t)(bm + row) * K + k0 + c4];
            As[row][c4 + 0] = tf32_of(v.x); As[row][c4 + 1] = tf32_of(v.y);
            As[row][c4 + 2] = tf32_of(v.z); As[row][c4 + 3] = tf32_of(v.w);
        }
#pragma unroll
        for (int i = 0; i < 2; i++) {
            const int f = tid + i * 256;
            const int row = f >> 3, c4 = (f & 7) * 4;
            const float4 v = *(const float4*)&B[(size_t)(bn + row) * K + k0 + c4];
            Bs[row][c4 + 0] = tf32_of(v.x); Bs[row][c4 + 1] = tf32_of(v.y);
            Bs[row][c4 + 2] = tf32_of(v.z); Bs[row][c4 + 3] = tf32_of(v.w);
        }
        __syncthreads();

#pragma unroll
        for (int ks = 0; ks < 4; ks++) {
            const int kb = ks * 8;
            unsigned a[2][4], bf[4][2];
#pragma unroll
            for (int mi = 0; mi < 2; mi++) {
                const int r0 = wm * 32 + mi * 16 + g;
                a[mi][0] = As[r0][kb + tg];
                a[mi][1] = As[r0 + 8][kb + tg];
                a[mi][2] = As[r0][kb + tg + 4];
                a[mi][3] = As[r0 + 8][kb + tg + 4];
            }
#pragma unroll
            for (int ni = 0; ni < 4; ni++) {
                const int n0 = wn * 32 + ni * 8 + g;
                bf[ni][0] = Bs[n0][kb + tg];
                bf[ni][1] = Bs[n0][kb + tg + 4];
            }
#pragma unroll
            for (int mi = 0; mi < 2; mi++)
#pragma unroll
                for (int ni = 0; ni < 4; ni++)
                    asm("mma.sync.aligned.m16n8k8.row.col.f32.tf32.tf32.f32 "
                        "{%0,%1,%2,%3},{%4,%5,%6,%7},{%8,%9},{%0,%1,%2,%3};"
                        : "+f"(acc[mi][ni][0]), "+f"(acc[mi][ni][1]),
                          "+f"(acc[mi][ni][2]), "+f"(acc[mi][ni][3])
                        : "r"(a[mi][0]), "r"(a[mi][1]), "r"(a[mi][2]), "r"(a[mi][3]),
                          "r"(bf[ni][0]), "r"(bf[ni][1]));
        }
        __syncthreads();
    }

#pragma unroll
    for (int mi = 0; mi < 2; mi++) {
        const int r0 = bm + wm * 32 + mi * 16 + g;
#pragma unroll
        for (int ni = 0; ni < 4; ni++) {
            const int c0 = bn + wn * 32 + ni * 8 + tg * 2;
            const float b0 = bias[c0], b1 = bias[c0 + 1];
            float2 v0 = { acc[mi][ni][0] + b0, acc[mi][ni][1] + b1 };
            float2 v1 = { acc[mi][ni][2] + b0, acc[mi][ni][3] + b1 };
            if (RELU) {
                v0.x = fmaxf(v0.x, 0.f); v0.y = fmaxf(v0.y, 0.f);
                v1.x = fmaxf(v1.x, 0.f); v1.y = fmaxf(v1.y, 0.f);
            }
            *(float2*)&C[(size_t)r0 * N + c0]       = v0;
            *(float2*)&C[(size_t)(r0 + 8) * N + c0] = v1;
        }
    }
}

// ---------------------------------------------------------------------------
// 7) fused attention: one block per (b,h), 256 threads, 3 queries per thread.
//    K/V staged once in smem; each K/V vector read once per warp and reused
//    across the 3 queries (cuts smem broadcast port traffic 3x vs R2).
//    Online softmax, chunk-4, conditional rescale.
// ---------------------------------------------------------------------------
__global__ __launch_bounds__(256) void attn_kernel()
{
    extern __shared__ u64 sm2[];
    u64* Ks = sm2;                  // [768][8] packed pairs
    u64* Vs = sm2 + KTOK * 8;

    const int h = blockIdx.x, b = blockIdx.y;
    const int tid = threadIdx.x;
    const float* qkv = g_qkv + (size_t)b * KTOK * 384;

    for (int e = tid; e < KTOK * 8; e += 256) {
        const int j = e >> 3, d = e & 7;
        Ks[e] = *(const u64*)&qkv[(size_t)j * 384 + 128 + h * HD + d * 2];
        Vs[e] = *(const u64*)&qkv[(size_t)j * 384 + 256 + h * HD + d * 2];
    }
    __syncthreads();

    u64 qv[3][8], acc[3][8];
    float m[3], l[3];
    const u64 sc = dup2(0.25f);     // 1/sqrt(16)
#pragma unroll
    for (int r = 0; r < 3; r++) {
        const u64* qp = (const u64*)(qkv + (size_t)(r * 256 + tid) * 384 + h * HD);
#pragma unroll
        for (int d = 0; d < 8; d++) { qv[r][d] = fmul2(qp[d], sc); acc[r][d] = 0ull; }
        m[r] = -1e30f; l[r] = 0.f;
    }

    for (int j0 = 0; j0 < KTOK; j0 += 4) {
        float s[3][4];
#pragma unroll
        for (int jj = 0; jj < 4; jj++) {
            const ulonglong2* kp = (const ulonglong2*)&Ks[(size_t)(j0 + jj) * 8];
            const ulonglong2 k0 = kp[0], k1 = kp[1], k2 = kp[2], k3 = kp[3];
#pragma unroll
            for (int r = 0; r < 3; r++) {
                u64 d2 = fmul2(qv[r][0], k0.x);
                ffma2(d2, qv[r][1], k0.y);
                ffma2(d2, qv[r][2], k1.x);
                ffma2(d2, qv[r][3], k1.y);
                ffma2(d2, qv[r][4], k2.x);
                ffma2(d2, qv[r][5], k2.y);
                ffma2(d2, qv[r][6], k3.x);
                ffma2(d2, qv[r][7], k3.y);
                const float2 t = unpack2(d2);
                s[r][jj] = t.x + t.y;
            }
        }
#pragma unroll
        for (int r = 0; r < 3; r++) {
            const float cm = fmaxf(fmaxf(s[r][0], s[r][1]), fmaxf(s[r][2], s[r][3]));
            if (cm > m[r]) {
                const float scal = __expf(m[r] - cm);
                l[r] *= scal;
                const u64 s2d = dup2(scal);
#pragma unroll
                for (int d = 0; d < 8; d++) acc[r][d] = fmul2(acc[r][d], s2d);
                m[r] = cm;
            }
#pragma unroll
            for (int jj = 0; jj < 4; jj++) {
                s[r][jj] = __expf(s[r][jj] - m[r]);
                l[r] += s[r][jj];
            }
        }
#pragma unroll
        for (int jj = 0; jj < 4; jj++) {
            const ulonglong2* vp = (const ulonglong2*)&Vs[(size_t)(j0 + jj) * 8];
            const ulonglong2 v0 = vp[0], v1 = vp[1], v2 = vp[2], v3 = vp[3];
#pragma unroll
            for (int r = 0; r < 3; r++) {
                const u64 e2 = dup2(s[r][jj]);
                ffma2(acc[r][0], e2, v0.x);
                ffma2(acc[r][1], e2, v0.y);
                ffma2(acc[r][2], e2, v1.x);
                ffma2(acc[r][3], e2, v1.y);
                ffma2(acc[r][4], e2, v2.x);
                ffma2(acc[r][5], e2, v2.y);
                ffma2(acc[r][6], e2, v3.x);
                ffma2(acc[r][7], e2, v3.y);
            }
        }
    }

#pragma unroll
    for (int r = 0; r < 3; r++) {
        const u64 iv = dup2(1.f / l[r]);
        float* orow = g_attn + ((size_t)b * KTOK + r * 256 + tid) * CCH + h * HD;
#pragma unroll
        for (int d = 0; d < 4; d++)
            *(ulonglong2*)(orow + d * 4) =
                make_ulonglong2(fmul2(acc[r][2 * d], iv), fmul2(acc[r][2 * d + 1], iv));
    }
}

// ---------------------------------------------------------------------------
// 8) residual + LayerNorm
// ---------------------------------------------------------------------------
__global__ void ln_kernel(const float* __restrict__ a, const float* __restrict__ r,
                          const float* __restrict__ g, const float* __restrict__ be,
                          float* __restrict__ out)
{
    const int row  = blockIdx.x * 8 + (threadIdx.x >> 5);
    const int lane = threadIdx.x & 31;
    const float4 va = ((const float4*)(a + (size_t)row * CCH))[lane];
    const float4 vr = ((const float4*)(r + (size_t)row * CCH))[lane];
    float4 t;
    t.x = va.x + vr.x; t.y = va.y + vr.y; t.z = va.z + vr.z; t.w = va.w + vr.w;
    float s  = t.x + t.y + t.z + t.w;
    float s2 = t.x*t.x + t.y*t.y + t.z*t.z + t.w*t.w;
#pragma unroll
    for (int o = 16; o > 0; o >>= 1) {
        s  += __shfl_xor_sync(0xffffffffu, s,  o);
        s2 += __shfl_xor_sync(0xffffffffu, s2, o);
    }
    const float mu  = s * (1.f / 128.f);
    const float var = s2 * (1.f / 128.f) - mu * mu;
    const float inv = rsqrtf(var + 1e-5f);
    const float4 gv = ((const float4*)g)[lane];
    const float4 bv = ((const float4*)be)[lane];
    float4 o;
    o.x = (t.x - mu) * inv * gv.x + bv.x;
    o.y = (t.y - mu) * inv * gv.y + bv.y;
    o.z = (t.z - mu) * inv * gv.z + bv.z;
    o.w = (t.w - mu) * inv * gv.w + bv.w;
    ((float4*)(out + (size_t)row * CCH))[lane] = o;
}

// ---------------------------------------------------------------------------
// 9) out = x * imp (everywhere), then scatter t2 at selected pixels
// ---------------------------------------------------------------------------
__global__ void xs_kernel(const float* __restrict__ x, float* __restrict__ out)
{
    const unsigned i = blockIdx.x * 256u + threadIdx.x;
    const unsigned total = (unsigned)BATCH * CCH * (PIX / 4);
    if (i >= total) return;
    const unsigned base = i * 4u;
    const unsigned p4 = base % PIX;
    const unsigned b  = (base / PIX) / CCH;
    const float4 xv = *(const float4*)(x + base);
    const float* ip = g_imp + (size_t)b * PIX + p4;
    float4 o;
    o.x = xv.x * ip[0]; o.y = xv.y * ip[1]; o.z = xv.z * ip[2]; o.w = xv.w * ip[3];
    *(float4*)(out + base) = o;
}

__global__ void scatter_kernel(float* __restrict__ out)
{
    const int b = blockIdx.y, k = blockIdx.x, c = threadIdx.x;
    const int p = g_idx[b * KTOK + k];
    out[((size_t)b * CCH + c) * PIX + p] = g_t2[((size_t)b * KTOK + k) * CCH + c];
}

// ---------------------------------------------------------------------------
// launch
// ---------------------------------------------------------------------------
extern "C" void kernel_launch(void* const* d_in, const int* in_sizes, int n_in,
                              void* d_out, int out_size)
{
    const float* x      = (const float*)d_in[0];
    const float* conv_w = (const float*)d_in[1];
    const float* conv_b = (const float*)d_in[2];
    const float* bn_g   = (const float*)d_in[3];
    const float* bn_b   = (const float*)d_in[4];
    const float* bn_m   = (const float*)d_in[5];
    const float* bn_v   = (const float*)d_in[6];
    const float* w_qkv  = (const float*)d_in[7];
    const float* b_qkv  = (const float*)d_in[8];
    const float* w_o    = (const float*)d_in[9];
    const float* b_o    = (const float*)d_in[10];
    const float* ln1_g  = (const float*)d_in[11];
    const float* ln1_b  = (const float*)d_in[12];
    const float* w1     = (const float*)d_in[13];
    const float* b1     = (const float*)d_in[14];
    const float* w2     = (const float*)d_in[15];
    const float* b2     = (const float*)d_in[16];
    const float* ln2_g  = (const float*)d_in[17];
    const float* ln2_b  = (const float*)d_in[18];
    float* out = (float*)d_out;

    float *p_tokens, *p_qkv, *p_attn, *p_t1, *p_h1, *p_tmp, *p_t2;
    cudaGetSymbolAddress((void**)&p_tokens, g_tokens);
    cudaGetSymbolAddress((void**)&p_qkv,    g_qkv);
    cudaGetSymbolAddress((void**)&p_attn,   g_attn);
    cudaGetSymbolAddress((void**)&p_t1,     g_t1);
    cudaGetSymbolAddress((void**)&p_h1,     g_h1);
    cudaGetSymbolAddress((void**)&p_tmp,    g_tmp);
    cudaGetSymbolAddress((void**)&p_t2,     g_t2);

    cudaFuncSetAttribute(topk_kernel, cudaFuncAttributeMaxDynamicSharedMemorySize,
                         PIX * (int)sizeof(unsigned));
    cudaFuncSetAttribute(attn_kernel, cudaFuncAttributeMaxDynamicSharedMemorySize,
                         2 * KTOK * HD * (int)sizeof(float));

    // conv -> importance -> top-K -> tokens
    freq_kernel<<<1, 64>>>();
    conv_kernel<<<dim3(4, 4, BATCH), 160>>>(x, conv_w);
    imp_kernel<<<(BATCH * PIX + 255) / 256, 256>>>(conv_b, bn_g, bn_b, bn_m, bn_v);
    topk_kernel<<<BATCH, 256, PIX * sizeof(unsigned)>>>();
    gather_kernel<<<dim3(KTOK, BATCH), CCH>>>(x);

    // transformer encoder layer (tf32 tensor-core GEMMs)
    gemm_tf32<false><<<dim3(384 / 64, NTOK / 128), 256>>>(p_tokens, w_qkv, b_qkv, p_qkv, NTOK, 384, 128);

    attn_kernel<<<dim3(NHEAD, BATCH), 256, 2 * KTOK * HD * sizeof(float)>>>();

    gemm_tf32<false><<<dim3(128 / 64, NTOK / 128), 256>>>(p_attn, w_o, b_o, p_tmp, NTOK, 128, 128);
    ln_kernel<<<NTOK / 8, 256>>>(p_tokens, p_tmp, ln1_g, ln1_b, p_t1);
    gemm_tf32<true ><<<dim3(256 / 64, NTOK / 128), 256>>>(p_t1, w1, b1, p_h1, NTOK, 256, 128);
    gemm_tf32<false><<<dim3(128 / 64, NTOK / 128), 256>>>(p_h1, w2, b2, p_tmp, NTOK, 128, 256);
    ln_kernel<<<NTOK / 8, 256>>>(p_t1, p_tmp, ln2_g, ln2_b, p_t2);

    // assemble output
    xs_kernel<<<(BATCH * CCH * (PIX / 4) + 255) / 256, 256>>>(x, out);
    scatter_kernel<<<dim3(KTOK, BATCH), CCH>>>(out);
}

// round 5
// speedup vs baseline: 1.3664x; 1.2089x over previous
#include <cuda_runtime.h>
#include <cuda_bf16.h>
#include <math.h>

// ---------------------------------------------------------------------------
// Problem constants
// ---------------------------------------------------------------------------
#define BATCH 32
#define CCH   128           // channels / d_model
#define HH    110           // spatial
#define PIX   (HH*HH)       // 12100
#define KTOK  768
#define NHEAD 8
#define HD    16
#define NTOK  (BATCH*KTOK)  // 24576

typedef unsigned long long u64;

// ---------------------------------------------------------------------------
// packed fp32x2 helpers (Blackwell FFMA2 path — only reachable via PTX)
// ---------------------------------------------------------------------------
__device__ __forceinline__ void ffma2(u64 &d, u64 a, u64 b) {
    asm("fma.rn.f32x2 %0, %1, %2, %0;" : "+l"(d) : "l"(a), "l"(b));
}
__device__ __forceinline__ u64 dup2(float x) {
    u64 d; asm("mov.b64 %0, {%1, %1};" : "=l"(d) : "f"(x)); return d;
}
__device__ __forceinline__ u64 pack2(float x, float y) {
    u64 d; asm("mov.b64 %0, {%1, %2};" : "=l"(d) : "f"(x), "f"(y)); return d;
}
__device__ __forceinline__ float2 unpack2(u64 v) {
    float2 r; asm("mov.b64 {%0, %1}, %2;" : "=f"(r.x), "=f"(r.y) : "l"(v)); return r;
}
__device__ __forceinline__ unsigned tf32_of(float x) {
    unsigned r; asm("cvt.rna.tf32.f32 %0, %1;" : "=r"(r) : "f"(x)); return r;
}
// tf32-rounded float (bits valid as both f32 and tf32 operand)
__device__ __forceinline__ float tf32f(float x) {
    return __uint_as_float(tf32_of(x));
}
__device__ __forceinline__ void mma_tf32(float* c, const unsigned* a, const unsigned* b) {
    asm("mma.sync.aligned.m16n8k8.row.col.f32.tf32.tf32.f32 "
        "{%0,%1,%2,%3},{%4,%5,%6,%7},{%8,%9},{%0,%1,%2,%3};"
        : "+f"(c[0]), "+f"(c[1]), "+f"(c[2]), "+f"(c[3])
        : "r"(a[0]), "r"(a[1]), "r"(a[2]), "r"(a[3]), "r"(b[0]), "r"(b[1]));
}

// ---------------------------------------------------------------------------
// Scratch (static device globals; no allocation allowed)
// ---------------------------------------------------------------------------
__device__ float g_y[4][BATCH*PIX];          // conv partial sums (4 channel chunks)
__device__ float g_imp[BATCH*PIX];           // importance map
__device__ int   g_idx[BATCH*KTOK];          // selected (sorted) pixel indices
__device__ float g_freq[64];                 // positional-encoding frequencies
__device__ float g_tokens[NTOK*CCH];
__device__ float g_qkv[NTOK*3*CCH];
__device__ float g_attn[NTOK*CCH];
__device__ float g_t1[NTOK*CCH];
__device__ float g_h1[NTOK*2*CCH];
__device__ float g_tmp[NTOK*CCH];
__device__ float g_t2[NTOK*CCH];

// ---------------------------------------------------------------------------
// 1) Dilated conv (k=7, d=5, p=15), residue decomposition + f32x2 packing.
// ---------------------------------------------------------------------------
__global__ void conv_kernel(const float* __restrict__ x, const float* __restrict__ w)
{
    __shared__ float tile[62][140];
    __shared__ float ws[49];

    const int cc  = blockIdx.x;
    const int rc  = blockIdx.y;
    const int b   = blockIdx.z;
    const int tid = threadIdx.x;

    const int r_local = tid / 5;
    const int res     = tid % 5;
    const int row0    = rc * 32;
    const int nrows   = min(32, HH - row0);
    const bool active = (r_local < nrows);

    for (int e = tid; e < 62 * 140; e += 160)
        ((float*)tile)[e] = 0.f;

    u64 acc[11];
#pragma unroll
    for (int p = 0; p < 11; p++) acc[p] = 0ull;

    for (int ci = 0; ci < 32; ci++) {
        const int c = cc * 32 + ci;
        __syncthreads();
        if (tid < 49) ws[tid] = w[c * 49 + tid];
        const float* xp = x + ((size_t)b * CCH + c) * PIX;
        for (int e = tid; e < 62 * 110; e += 160) {
            const int tr = e / 110, tc = e % 110;
            const int gr = row0 - 15 + tr;
            tile[tr][15 + tc] = (gr >= 0 && gr < HH) ? xp[gr * HH + tc] : 0.f;
        }
        __syncthreads();

        if (active) {
#pragma unroll
            for (int u = 0; u < 7; u++) {
                const int trow = r_local + 5 * u;
                u64 xp2[27];
                float prev = tile[trow][res];
#pragma unroll
                for (int t = 0; t < 27; t++) {
                    const float cur = tile[trow][res + 5 * (t + 1)];
                    xp2[t] = pack2(prev, cur);
                    prev = cur;
                }
#pragma unroll
                for (int v = 0; v < 7; v++) {
                    const u64 wd = dup2(ws[u * 7 + v]);
#pragma unroll
                    for (int p = 0; p < 11; p++)
                        ffma2(acc[p], wd, xp2[2 * p + v]);
                }
            }
        }
    }

    if (active) {
        const int orow = row0 + r_local;
#pragma unroll
        for (int p = 0; p < 11; p++) {
            const float2 t = unpack2(acc[p]);
            g_y[cc][b * PIX + orow * HH + res + 5 * (2 * p)]     = t.x;
            g_y[cc][b * PIX + orow * HH + res + 5 * (2 * p + 1)] = t.y;
        }
    }
}

// ---------------------------------------------------------------------------
// 2) importance = sigmoid(gelu(BN(conv + bias)))
// ---------------------------------------------------------------------------
__global__ void imp_kernel(const float* __restrict__ cb, const float* __restrict__ bg,
                           const float* __restrict__ bb, const float* __restrict__ bm,
                           const float* __restrict__ bv)
{
    const int i = blockIdx.x * 256 + threadIdx.x;
    if (i >= BATCH * PIX) return;
    float y = g_y[0][i] + g_y[1][i] + g_y[2][i] + g_y[3][i] + cb[0];
    const float scale = bg[0] * rsqrtf(bv[0] + 1e-5f);
    y = (y - bm[0]) * scale + bb[0];
    const float g = 0.5f * y * (1.f + erff(y * 0.70710678118654752f));
    g_imp[i] = 1.f / (1.f + expf(-g));
}

// ---------------------------------------------------------------------------
// 3) top-K per batch (radix-256 threshold + ballot compaction)
// ---------------------------------------------------------------------------
#define NCHK ((PIX + 255) / 256)   // 48

__global__ void topk_kernel()
{
    extern __shared__ unsigned sbits[];     // [PIX]
    __shared__ int hist[256];
    __shared__ int cgt[NCHK], ceq[NCHK];
    __shared__ unsigned sh_prefix;
    __shared__ int sh_above;

    const int b    = blockIdx.x;
    const int tid  = threadIdx.x;
    const int lane = tid & 31;
    const int wrp  = tid >> 5;
    const float* v = g_imp + b * PIX;

    for (int i = tid; i < PIX; i += 256)
        sbits[i] = __float_as_uint(v[i]);
    __syncthreads();

    unsigned prefix = 0;
    int kneed = KTOK;

#pragma unroll
    for (int shift = 24; shift >= 0; shift -= 8) {
        hist[tid] = 0;
        __syncthreads();
        const unsigned pm = (shift == 24) ? 0u : (0xFFFFFFFFu << (shift + 8));
        for (int i = tid; i < PIX; i += 256) {
            const unsigned bits = sbits[i];
            if ((bits & pm) == prefix)
                atomicAdd(&hist[(bits >> shift) & 255], 1);
        }
        __syncthreads();
        for (int off = 1; off < 256; off <<= 1) {
            const int val = (tid + off < 256) ? hist[tid + off] : 0;
            __syncthreads();
            hist[tid] += val;
            __syncthreads();
        }
        const int here  = hist[tid];
        const int above = (tid == 255) ? 0 : hist[tid + 1];
        if (here >= kneed && above < kneed) {
            sh_prefix = prefix | ((unsigned)tid << shift);
            sh_above  = above;
        }
        __syncthreads();
        prefix = sh_prefix;
        kneed -= sh_above;
        __syncthreads();
    }

    const unsigned T = prefix;
    const int tn = kneed;

    for (int c = wrp; c < NCHK; c += 8) {
        int gt = 0, eq = 0;
#pragma unroll
        for (int g = 0; g < 8; g++) {
            const int i = c * 256 + g * 32 + lane;
            const unsigned bits = (i < PIX) ? sbits[i] : 0u;
            const unsigned bg = __ballot_sync(0xffffffffu, bits > T);
            const unsigned be = __ballot_sync(0xffffffffu, bits == T && i < PIX);
            gt += __popc(bg); eq += __popc(be);
        }
        if (lane == 0) { cgt[c] = gt; ceq[c] = eq; }
    }
    __syncthreads();
    if (tid == 0) {
        int sg = 0, se = 0;
        for (int c = 0; c < NCHK; c++) {
            const int tg = cgt[c], te = ceq[c];
            cgt[c] = sg; ceq[c] = se;
            sg += tg; se += te;
        }
    }
    __syncthreads();

    const unsigned lmask = (1u << lane) - 1u;
    for (int c = wrp; c < NCHK; c += 8) {
        int gt_run = cgt[c], eq_run = ceq[c];
#pragma unroll
        for (int g = 0; g < 8; g++) {
            const int i = c * 256 + g * 32 + lane;
            const unsigned bits = (i < PIX) ? sbits[i] : 0u;
            const bool isgt = bits > T;
            const bool iseq = (bits == T) && (i < PIX);
            const unsigned bg = __ballot_sync(0xffffffffu, isgt);
            const unsigned be = __ballot_sync(0xffffffffu, iseq);
            const int gt_before = gt_run + __popc(bg & lmask);
            const int eq_before = eq_run + __popc(be & lmask);
            if (isgt)
                g_idx[b * KTOK + gt_before + min(eq_before, tn)] = i;
            else if (iseq && eq_before < tn)
                g_idx[b * KTOK + gt_before + eq_before] = i;
            gt_run += __popc(bg);
            eq_run += __popc(be);
        }
    }
}

// ---------------------------------------------------------------------------
// 4) positional-encoding frequency table
// ---------------------------------------------------------------------------
__global__ void freq_kernel()
{
    const int i = threadIdx.x;           // 64
    const float cst = (float)(-(log(10000.0) / 128.0));
    const float a = (float)(2 * i) * cst;
    g_freq[i] = (float)exp((double)a);
}

// ---------------------------------------------------------------------------
// 5) gather tokens: tokens[b,k,c] = x[b,c,p]*imp[b,p] + PE[p,c]
// ---------------------------------------------------------------------------
__global__ void gather_kernel(const float* __restrict__ x)
{
    const int b = blockIdx.y, k = blockIdx.x, c = threadIdx.x;
    const int p = g_idx[b * KTOK + k];
    const float val = x[((size_t)b * CCH + c) * PIX + p] * g_imp[b * PIX + p];
    const float arg = (float)p * g_freq[c >> 1];
    const float pe  = (c & 1) ? cosf(arg) : sinf(arg);
    g_tokens[((size_t)b * KTOK + k) * CCH + c] = val + pe;
}

// ---------------------------------------------------------------------------
// 6) tf32 tensor-core GEMM: C[m,n] = act( sum_k A[m,k]*B[n,k] + bias[n] )
// ---------------------------------------------------------------------------
template <bool RELU>
__global__ __launch_bounds__(256) void gemm_tf32(
    const float* __restrict__ A, const float* __restrict__ B,
    const float* __restrict__ bias, float* __restrict__ C,
    int M, int N, int K)
{
    __shared__ unsigned As[128][33];
    __shared__ unsigned Bs[64][33];

    const int tid  = threadIdx.x;
    const int lane = tid & 31;
    const int wid  = tid >> 5;
    const int wm   = wid >> 1;
    const int wn   = wid & 1;
    const int g    = lane >> 2;
    const int tg   = lane & 3;
    const int bm   = blockIdx.y * 128, bn = blockIdx.x * 64;

    float acc[2][4][4];
#pragma unroll
    for (int mi = 0; mi < 2; mi++)
#pragma unroll
        for (int ni = 0; ni < 4; ni++)
#pragma unroll
            for (int e = 0; e < 4; e++) acc[mi][ni][e] = 0.f;

    for (int k0 = 0; k0 < K; k0 += 32) {
#pragma unroll
        for (int i = 0; i < 4; i++) {
            const int f = tid + i * 256;
            const int row = f >> 3, c4 = (f & 7) * 4;
            const float4 v = *(const float4*)&A[(size_t)(bm + row) * K + k0 + c4];
            As[row][c4 + 0] = tf32_of(v.x); As[row][c4 + 1] = tf32_of(v.y);
            As[row][c4 + 2] = tf32_of(v.z); As[row][c4 + 3] = tf32_of(v.w);
        }
#pragma unroll
        for (int i = 0; i < 2; i++) {
            const int f = tid + i * 256;
            const int row = f >> 3, c4 = (f & 7) * 4;
            const float4 v = *(const float4*)&B[(size_t)(bn + row) * K + k0 + c4];
            Bs[row][c4 + 0] = tf32_of(v.x); Bs[row][c4 + 1] = tf32_of(v.y);
            Bs[row][c4 + 2] = tf32_of(v.z); Bs[row][c4 + 3] = tf32_of(v.w);
        }
        __syncthreads();

#pragma unroll
        for (int ks = 0; ks < 4; ks++) {
            const int kb = ks * 8;
            unsigned a[2][4], bf[4][2];
#pragma unroll
            for (int mi = 0; mi < 2; mi++) {
                const int r0 = wm * 32 + mi * 16 + g;
                a[mi][0] = As[r0][kb + tg];
                a[mi][1] = As[r0 + 8][kb + tg];
                a[mi][2] = As[r0][kb + tg + 4];
                a[mi][3] = As[r0 + 8][kb + tg + 4];
            }
#pragma unroll
            for (int ni = 0; ni < 4; ni++) {
                const int n0 = wn * 32 + ni * 8 + g;
                bf[ni][0] = Bs[n0][kb + tg];
                bf[ni][1] = Bs[n0][kb + tg + 4];
            }
#pragma unroll
            for (int mi = 0; mi < 2; mi++)
#pragma unroll
                for (int ni = 0; ni < 4; ni++)
                    mma_tf32(acc[mi][ni], a[mi], bf[ni]);
        }
        __syncthreads();
    }

#pragma unroll
    for (int mi = 0; mi < 2; mi++) {
        const int r0 = bm + wm * 32 + mi * 16 + g;
#pragma unroll
        for (int ni = 0; ni < 4; ni++) {
            const int c0 = bn + wn * 32 + ni * 8 + tg * 2;
            const float b0 = bias[c0], b1 = bias[c0 + 1];
            float2 v0 = { acc[mi][ni][0] + b0, acc[mi][ni][1] + b1 };
            float2 v1 = { acc[mi][ni][2] + b0, acc[mi][ni][3] + b1 };
            if (RELU) {
                v0.x = fmaxf(v0.x, 0.f); v0.y = fmaxf(v0.y, 0.f);
                v1.x = fmaxf(v1.x, 0.f); v1.y = fmaxf(v1.y, 0.f);
            }
            *(float2*)&C[(size_t)r0 * N + c0]       = v0;
            *(float2*)&C[(size_t)(r0 + 8) * N + c0] = v1;
        }
    }
}

// ---------------------------------------------------------------------------
// 7) tensor-core flash attention. One block per (b,h), 512 threads = 16 warps.
//    Each warp owns 48 query rows (3 m16 tiles). K/V staged per 256-key chunk
//    into smem as tf32. S = Q K^T and O += P V via mma.m16n8k8 tf32 with
//    online softmax on the C fragments (row stats across the lane quad).
// ---------------------------------------------------------------------------
__global__ __launch_bounds__(512) void attn_kernel()
{
    __shared__ unsigned sK[256][18];   // keys x dims (padded, conflict-light)
    __shared__ unsigned sV[256][24];   // keys x dims (conflict-free B reads)

    const int h = blockIdx.x, b = blockIdx.y;
    const int tid  = threadIdx.x;
    const int lane = tid & 31;
    const int w    = tid >> 5;           // 0..15
    const int g    = lane >> 2;          // 0..7
    const int tg   = lane & 3;           // 0..3
    const float* qkv = g_qkv + (size_t)b * KTOK * 384;

    // Q fragments (pre-scaled by 1/sqrt(hd)=0.25), 3 q-tiles per warp
    unsigned qa[3][8];
#pragma unroll
    for (int qt = 0; qt < 3; qt++) {
        const int row = w * 48 + qt * 16 + g;
        const float* q0 = qkv + (size_t)row * 384 + h * 16;
        const float* q8 = q0 + 8 * 384;
        qa[qt][0] = tf32_of(q0[tg]      * 0.25f);
        qa[qt][1] = tf32_of(q8[tg]      * 0.25f);
        qa[qt][2] = tf32_of(q0[tg + 4]  * 0.25f);
        qa[qt][3] = tf32_of(q8[tg + 4]  * 0.25f);
        qa[qt][4] = tf32_of(q0[tg + 8]  * 0.25f);
        qa[qt][5] = tf32_of(q8[tg + 8]  * 0.25f);
        qa[qt][6] = tf32_of(q0[tg + 12] * 0.25f);
        qa[qt][7] = tf32_of(q8[tg + 12] * 0.25f);
    }

    float m[3][2], l[3][2], o[3][2][4];
#pragma unroll
    for (int qt = 0; qt < 3; qt++) {
        m[qt][0] = m[qt][1] = -1e30f;
        l[qt][0] = l[qt][1] = 0.f;
#pragma unroll
        for (int n = 0; n < 2; n++)
#pragma unroll
            for (int e = 0; e < 4; e++) o[qt][n][e] = 0.f;
    }

    const int src0 = (lane & 28) | (tg >> 1);   // P-shuffle source lanes
    const int src2 = src0 + 2;

    for (int ch = 0; ch < 3; ch++) {
        __syncthreads();
        for (int e = tid; e < 256 * 16; e += 512) {
            const int j = e >> 4, d = e & 15;
            const size_t base = (size_t)(ch * 256 + j) * 384 + h * 16 + d;
            sK[j][d] = tf32_of(qkv[base + 128]);
            sV[j][d] = tf32_of(qkv[base + 256]);
        }
        __syncthreads();

        for (int sub = 0; sub < 8; sub++) {       // 32 keys per sub-chunk
            unsigned kb[4][2][2];                 // B frags for S (shared by qts)
#pragma unroll
            for (int t = 0; t < 4; t++) {
                const int key = sub * 32 + t * 8 + g;
                kb[t][0][0] = sK[key][tg];
                kb[t][0][1] = sK[key][tg + 4];
                kb[t][1][0] = sK[key][tg + 8];
                kb[t][1][1] = sK[key][tg + 12];
            }
#pragma unroll
            for (int qt = 0; qt < 3; qt++) {
                // scores
                float s[4][4];
#pragma unroll
                for (int t = 0; t < 4; t++) {
                    s[t][0] = s[t][1] = s[t][2] = s[t][3] = 0.f;
                    mma_tf32(s[t], qa[qt],     kb[t][0]);
                    mma_tf32(s[t], qa[qt] + 4, kb[t][1]);
                }
                // row maxima (rows g and g+8), reduced across the quad
                float mx0 = s[0][0], mx1 = s[0][2];
#pragma unroll
                for (int t = 0; t < 4; t++) {
                    mx0 = fmaxf(mx0, fmaxf(s[t][0], s[t][1]));
                    mx1 = fmaxf(mx1, fmaxf(s[t][2], s[t][3]));
                }
                mx0 = fmaxf(mx0, __shfl_xor_sync(0xffffffffu, mx0, 1));
                mx0 = fmaxf(mx0, __shfl_xor_sync(0xffffffffu, mx0, 2));
                mx1 = fmaxf(mx1, __shfl_xor_sync(0xffffffffu, mx1, 1));
                mx1 = fmaxf(mx1, __shfl_xor_sync(0xffffffffu, mx1, 2));
                const float nm0 = fmaxf(m[qt][0], mx0);
                const float nm1 = fmaxf(m[qt][1], mx1);
                const float f0 = __expf(m[qt][0] - nm0);
                const float f1 = __expf(m[qt][1] - nm1);
                m[qt][0] = nm0; m[qt][1] = nm1;
                // exp, tf32-round, partial row sums
                float s0 = 0.f, s1 = 0.f;
#pragma unroll
                for (int t = 0; t < 4; t++) {
                    s[t][0] = tf32f(__expf(s[t][0] - nm0));
                    s[t][1] = tf32f(__expf(s[t][1] - nm0));
                    s[t][2] = tf32f(__expf(s[t][2] - nm1));
                    s[t][3] = tf32f(__expf(s[t][3] - nm1));
                    s0 += s[t][0] + s[t][1];
                    s1 += s[t][2] + s[t][3];
                }
                l[qt][0] = l[qt][0] * f0 + s0;
                l[qt][1] = l[qt][1] * f1 + s1;
                // rescale O
#pragma unroll
                for (int n = 0; n < 2; n++) {
                    o[qt][n][0] *= f0; o[qt][n][1] *= f0;
                    o[qt][n][2] *= f1; o[qt][n][3] *= f1;
                }
                // P @ V
#pragma unroll
                for (int t = 0; t < 4; t++) {
                    // rearrange C frag -> A frag (P[16 x 8keys])
                    unsigned a[4];
                    {
                        const float t00 = __shfl_sync(0xffffffffu, s[t][0], src0);
                        const float t01 = __shfl_sync(0xffffffffu, s[t][1], src0);
                        const float t10 = __shfl_sync(0xffffffffu, s[t][2], src0);
                        const float t11 = __shfl_sync(0xffffffffu, s[t][3], src0);
                        a[0] = __float_as_uint((tg & 1) ? t01 : t00);
                        a[1] = __float_as_uint((tg & 1) ? t11 : t10);
                        const float u00 = __shfl_sync(0xffffffffu, s[t][0], src2);
                        const float u01 = __shfl_sync(0xffffffffu, s[t][1], src2);
                        const float u10 = __shfl_sync(0xffffffffu, s[t][2], src2);
                        const float u11 = __shfl_sync(0xffffffffu, s[t][3], src2);
                        a[2] = __float_as_uint((tg & 1) ? u01 : u00);
                        a[3] = __float_as_uint((tg & 1) ? u11 : u10);
                    }
                    const int key = sub * 32 + t * 8;
                    unsigned vb0[2], vb1[2];
                    vb0[0] = sV[key + tg][g];         vb0[1] = sV[key + tg + 4][g];
                    vb1[0] = sV[key + tg][g + 8];     vb1[1] = sV[key + tg + 4][g + 8];
                    mma_tf32(o[qt][0], a, vb0);
                    mma_tf32(o[qt][1], a, vb1);
                }
            }
        }
    }

    // finalize: quad-reduce l, normalize, store
#pragma unroll
    for (int qt = 0; qt < 3; qt++) {
        float l0 = l[qt][0], l1 = l[qt][1];
        l0 += __shfl_xor_sync(0xffffffffu, l0, 1);
        l0 += __shfl_xor_sync(0xffffffffu, l0, 2);
        l1 += __shfl_xor_sync(0xffffffffu, l1, 1);
        l1 += __shfl_xor_sync(0xffffffffu, l1, 2);
        const float inv0 = 1.f / l0, inv1 = 1.f / l1;
        const int row = w * 48 + qt * 16 + g;
        float* out0 = g_attn + ((size_t)b * KTOK + row) * CCH + h * 16 + tg * 2;
        float* out8 = out0 + 8 * CCH;
#pragma unroll
        for (int n = 0; n < 2; n++) {
            *(float2*)(out0 + n * 8) = make_float2(o[qt][n][0] * inv0, o[qt][n][1] * inv0);
            *(float2*)(out8 + n * 8) = make_float2(o[qt][n][2] * inv1, o[qt][n][3] * inv1);
        }
    }
}

// ---------------------------------------------------------------------------
// 8) residual + LayerNorm
// ---------------------------------------------------------------------------
__global__ void ln_kernel(const float* __restrict__ a, const float* __restrict__ r,
                          const float* __restrict__ g, const float* __restrict__ be,
                          float* __restrict__ out)
{
    const int row  = blockIdx.x * 8 + (threadIdx.x >> 5);
    const int lane = threadIdx.x & 31;
    const float4 va = ((const float4*)(a + (size_t)row * CCH))[lane];
    const float4 vr = ((const float4*)(r + (size_t)row * CCH))[lane];
    float4 t;
    t.x = va.x + vr.x; t.y = va.y + vr.y; t.z = va.z + vr.z; t.w = va.w + vr.w;
    float s  = t.x + t.y + t.z + t.w;
    float s2 = t.x*t.x + t.y*t.y + t.z*t.z + t.w*t.w;
#pragma unroll
    for (int o = 16; o > 0; o >>= 1) {
        s  += __shfl_xor_sync(0xffffffffu, s,  o);
        s2 += __shfl_xor_sync(0xffffffffu, s2, o);
    }
    const float mu  = s * (1.f / 128.f);
    const float var = s2 * (1.f / 128.f) - mu * mu;
    const float inv = rsqrtf(var + 1e-5f);
    const float4 gv = ((const float4*)g)[lane];
    const float4 bv = ((const float4*)be)[lane];
    float4 o;
    o.x = (t.x - mu) * inv * gv.x + bv.x;
    o.y = (t.y - mu) * inv * gv.y + bv.y;
    o.z = (t.z - mu) * inv * gv.z + bv.z;
    o.w = (t.w - mu) * inv * gv.w + bv.w;
    ((float4*)(out + (size_t)row * CCH))[lane] = o;
}

// ---------------------------------------------------------------------------
// 9) out = x * imp (everywhere), then scatter t2 at selected pixels
// ---------------------------------------------------------------------------
__global__ void xs_kernel(const float* __restrict__ x, float* __restrict__ out)
{
    const unsigned i = blockIdx.x * 256u + threadIdx.x;
    const unsigned total = (unsigned)BATCH * CCH * (PIX / 4);
    if (i >= total) return;
    const unsigned base = i * 4u;
    const unsigned p4 = base % PIX;
    const unsigned b  = (base / PIX) / CCH;
    const float4 xv = *(const float4*)(x + base);
    const float* ip = g_imp + (size_t)b * PIX + p4;
    float4 o;
    o.x = xv.x * ip[0]; o.y = xv.y * ip[1]; o.z = xv.z * ip[2]; o.w = xv.w * ip[3];
    *(float4*)(out + base) = o;
}

__global__ void scatter_kernel(float* __restrict__ out)
{
    const int b = blockIdx.y, k = blockIdx.x, c = threadIdx.x;
    const int p = g_idx[b * KTOK + k];
    out[((size_t)b * CCH + c) * PIX + p] = g_t2[((size_t)b * KTOK + k) * CCH + c];
}

// ---------------------------------------------------------------------------
// launch
// ---------------------------------------------------------------------------
extern "C" void kernel_launch(void* const* d_in, const int* in_sizes, int n_in,
                              void* d_out, int out_size)
{
    const float* x      = (const float*)d_in[0];
    const float* conv_w = (const float*)d_in[1];
    const float* conv_b = (const float*)d_in[2];
    const float* bn_g   = (const float*)d_in[3];
    const float* bn_b   = (const float*)d_in[4];
    const float* bn_m   = (const float*)d_in[5];
    const float* bn_v   = (const float*)d_in[6];
    const float* w_qkv  = (const float*)d_in[7];
    const float* b_qkv  = (const float*)d_in[8];
    const float* w_o    = (const float*)d_in[9];
    const float* b_o    = (const float*)d_in[10];
    const float* ln1_g  = (const float*)d_in[11];
    const float* ln1_b  = (const float*)d_in[12];
    const float* w1     = (const float*)d_in[13];
    const float* b1     = (const float*)d_in[14];
    const float* w2     = (const float*)d_in[15];
    const float* b2     = (const float*)d_in[16];
    const float* ln2_g  = (const float*)d_in[17];
    const float* ln2_b  = (const float*)d_in[18];
    float* out = (float*)d_out;

    float *p_tokens, *p_qkv, *p_attn, *p_t1, *p_h1, *p_tmp, *p_t2;
    cudaGetSymbolAddress((void**)&p_tokens, g_tokens);
    cudaGetSymbolAddress((void**)&p_qkv,    g_qkv);
    cudaGetSymbolAddress((void**)&p_attn,   g_attn);
    cudaGetSymbolAddress((void**)&p_t1,     g_t1);
    cudaGetSymbolAddress((void**)&p_h1,     g_h1);
    cudaGetSymbolAddress((void**)&p_tmp,    g_tmp);
    cudaGetSymbolAddress((void**)&p_t2,     g_t2);

    cudaFuncSetAttribute(topk_kernel, cudaFuncAttributeMaxDynamicSharedMemorySize,
                         PIX * (int)sizeof(unsigned));

    // conv -> importance -> top-K -> tokens
    freq_kernel<<<1, 64>>>();
    conv_kernel<<<dim3(4, 4, BATCH), 160>>>(x, conv_w);
    imp_kernel<<<(BATCH * PIX + 255) / 256, 256>>>(conv_b, bn_g, bn_b, bn_m, bn_v);
    topk_kernel<<<BATCH, 256, PIX * sizeof(unsigned)>>>();
    gather_kernel<<<dim3(KTOK, BATCH), CCH>>>(x);

    // transformer encoder layer (tf32 tensor cores throughout)
    gemm_tf32<false><<<dim3(384 / 64, NTOK / 128), 256>>>(p_tokens, w_qkv, b_qkv, p_qkv, NTOK, 384, 128);

    attn_kernel<<<dim3(NHEAD, BATCH), 512>>>();

    gemm_tf32<false><<<dim3(128 / 64, NTOK / 128), 256>>>(p_attn, w_o, b_o, p_tmp, NTOK, 128, 128);
    ln_kernel<<<NTOK / 8, 256>>>(p_tokens, p_tmp, ln1_g, ln1_b, p_t1);
    gemm_tf32<true ><<<dim3(256 / 64, NTOK / 128), 256>>>(p_t1, w1, b1, p_h1, NTOK, 256, 128);
    gemm_tf32<false><<<dim3(128 / 64, NTOK / 128), 256>>>(p_h1, w2, b2, p_tmp, NTOK, 128, 256);
    ln_kernel<<<NTOK / 8, 256>>>(p_t1, p_tmp, ln2_g, ln2_b, p_t2);

    // assemble output
    xs_kernel<<<(BATCH * CCH * (PIX / 4) + 255) / 256, 256>>>(x, out);
    scatter_kernel<<<dim3(KTOK, BATCH), CCH>>>(out);
}

// round 6
// speedup vs baseline: 1.4178x; 1.0377x over previous
#include <cuda_runtime.h>
#include <cuda_bf16.h>
#include <math.h>

// ---------------------------------------------------------------------------
// Problem constants
// ---------------------------------------------------------------------------
#define BATCH 32
#define CCH   128           // channels / d_model
#define HH    110           // spatial
#define PIX   (HH*HH)       // 12100
#define KTOK  768
#define NHEAD 8
#define HD    16
#define NTOK  (BATCH*KTOK)  // 24576
#define YSTR  112           // padded row stride for y maps (16B-aligned rows)
#define CNT   128           // conv GEMM pixel tile
#define NPT   ((PIX + CNT - 1) / CNT)   // 95

typedef unsigned long long u64;

// ---------------------------------------------------------------------------
// helpers
// ---------------------------------------------------------------------------
__device__ __forceinline__ unsigned tf32_of(float x) {
    unsigned r; asm("cvt.rna.tf32.f32 %0, %1;" : "=r"(r) : "f"(x)); return r;
}
__device__ __forceinline__ float tf32f(float x) {
    return __uint_as_float(tf32_of(x));
}
__device__ __forceinline__ void split_tf32(float v, unsigned &hi, unsigned &lo) {
    hi = tf32_of(v);
    lo = tf32_of(v - __uint_as_float(hi));
}
__device__ __forceinline__ void mma_tf32(float* c, const unsigned* a, const unsigned* b) {
    asm("mma.sync.aligned.m16n8k8.row.col.f32.tf32.tf32.f32 "
        "{%0,%1,%2,%3},{%4,%5,%6,%7},{%8,%9},{%0,%1,%2,%3};"
        : "+f"(c[0]), "+f"(c[1]), "+f"(c[2]), "+f"(c[3])
        : "r"(a[0]), "r"(a[1]), "r"(a[2]), "r"(a[3]), "r"(b[0]), "r"(b[1]));
}

// ---------------------------------------------------------------------------
// Scratch (static device globals; no allocation allowed)
// ---------------------------------------------------------------------------
__device__ float g_yt[(size_t)BATCH*49*HH*YSTR];  // per-tap channel-reduced maps
__device__ float g_imp[BATCH*PIX];                // importance map
__device__ int   g_idx[BATCH*KTOK];               // selected (sorted) pixel indices
__device__ float g_freq[64];                      // positional-encoding frequencies
__device__ float g_tokens[NTOK*CCH];
__device__ float g_qkv[NTOK*3*CCH];
__device__ float g_attn[NTOK*CCH];
__device__ float g_t1[NTOK*CCH];
__device__ float g_h1[NTOK*2*CCH];
__device__ float g_tmp[NTOK*CCH];
__device__ float g_t2[NTOK*CCH];

// ---------------------------------------------------------------------------
// 1a) conv as GEMM (3xTF32, fp32-accurate): Y[t][p] = sum_c W[t][c] X[c][p].
//     M=64 (49 valid taps), N=128 pixels per block, K=128 channels.
//     grid (95 pixel-tiles, 32 batch), 256 threads (8 warps as 2m x 4n).
// ---------------------------------------------------------------------------
__global__ __launch_bounds__(256, 2) void convgemm_kernel(
    const float* __restrict__ x, const float* __restrict__ w)
{
    extern __shared__ float csm[];
    float (*As)[132] = (float(*)[132])csm;              // 64 x 132 (K=128 resident)
    float (*Bs)[132] = (float(*)[132])(csm + 64 * 132); // 32 x 132 per K-chunk

    const int pt = blockIdx.x, b = blockIdx.y;
    const int p0 = pt * CNT;
    const int tid = threadIdx.x, lane = tid & 31, wid = tid >> 5;
    const int wm = wid >> 2, wn = wid & 3;
    const int g = lane >> 2, tg = lane & 3;

    // A = W^T : As[t][c] = w[c*49 + t]; rows 49..63 zero
    for (int e = tid; e < 64 * 128; e += 256) {
        const int t = e & 63, c = e >> 6;
        As[t][c] = (t < 49) ? w[c * 49 + t] : 0.f;
    }

    float acc[2][4][4];
#pragma unroll
    for (int mi = 0; mi < 2; mi++)
#pragma unroll
        for (int ni = 0; ni < 4; ni++)
#pragma unroll
            for (int e = 0; e < 4; e++) acc[mi][ni][e] = 0.f;

    for (int k0 = 0; k0 < 128; k0 += 32) {
        __syncthreads();
        for (int e = tid; e < 32 * 128; e += 256) {
            const int c = e >> 7, p = e & 127;
            const int gp = p0 + p;
            Bs[c][p] = (gp < PIX) ? x[((size_t)b * CCH + k0 + c) * PIX + gp] : 0.f;
        }
        __syncthreads();
#pragma unroll
        for (int ks = 0; ks < 4; ks++) {
            const int kk = k0 + ks * 8 + tg;   // absolute k into As
            const int kb = ks * 8 + tg;        // local k into Bs
            unsigned ah[2][4], al[2][4];
#pragma unroll
            for (int mi = 0; mi < 2; mi++) {
                const int rr = wm * 32 + mi * 16 + g;
                split_tf32(As[rr][kk],       ah[mi][0], al[mi][0]);
                split_tf32(As[rr + 8][kk],   ah[mi][1], al[mi][1]);
                split_tf32(As[rr][kk + 4],   ah[mi][2], al[mi][2]);
                split_tf32(As[rr + 8][kk+4], ah[mi][3], al[mi][3]);
            }
#pragma unroll
            for (int ni = 0; ni < 4; ni++) {
                const int n0 = wn * 32 + ni * 8 + g;
                unsigned bh[2], bl[2];
                split_tf32(Bs[kb][n0],     bh[0], bl[0]);
                split_tf32(Bs[kb + 4][n0], bh[1], bl[1]);
#pragma unroll
                for (int mi = 0; mi < 2; mi++) {
                    mma_tf32(acc[mi][ni], ah[mi], bh);   // hi*hi
                    mma_tf32(acc[mi][ni], al[mi], bh);   // lo*hi
                    mma_tf32(acc[mi][ni], ah[mi], bl);   // hi*lo
                }
            }
        }
    }

    // store into padded [b][t][r][0..111] layout
#pragma unroll
    for (int mi = 0; mi < 2; mi++) {
        const int t = wm * 32 + mi * 16 + g;
#pragma unroll
        for (int ni = 0; ni < 4; ni++) {
            const int pcol = p0 + wn * 32 + ni * 8 + tg * 2;
            if (pcol < PIX) {
                const int r0r = pcol / HH, c0r = pcol - r0r * HH;
                const bool ok1 = (pcol + 1 < PIX);
                const int r1r = (pcol + 1) / HH, c1r = (pcol + 1) - r1r * HH;
                if (t < 49) {
                    float* yb = g_yt + ((size_t)b * 49 + t) * HH * YSTR;
                    yb[r0r * YSTR + c0r] = acc[mi][ni][0];
                    if (ok1) yb[r1r * YSTR + c1r] = acc[mi][ni][1];
                }
                if (t + 8 < 49) {
                    float* yb = g_yt + ((size_t)b * 49 + t + 8) * HH * YSTR;
                    yb[r0r * YSTR + c0r] = acc[mi][ni][2];
                    if (ok1) yb[r1r * YSTR + c1r] = acc[mi][ni][3];
                }
            }
        }
    }
}

// ---------------------------------------------------------------------------
// 1b) shift-add over 49 taps + BN + GELU + sigmoid -> importance map.
//     grid (7 row-chunks, 32 batch), 256 threads; 16 out rows x 110 cols.
// ---------------------------------------------------------------------------
__global__ __launch_bounds__(256) void convadd_kernel(
    const float* __restrict__ cb, const float* __restrict__ bg,
    const float* __restrict__ bb, const float* __restrict__ bm,
    const float* __restrict__ bv)
{
    __shared__ float sy[16][144];    // slab: col 16+gc holds y col gc (0..111)
    const int rc = blockIdx.x;       // 0..6
    const int b  = blockIdx.y;
    const int r0 = rc * 16;
    const int tid = threadIdx.x;

    for (int e = tid; e < 16 * 144 / 4; e += 256)
        ((float4*)sy)[e] = make_float4(0.f, 0.f, 0.f, 0.f);

    float acc[7];
#pragma unroll
    for (int o = 0; o < 7; o++) acc[o] = 0.f;

    for (int u = 0; u < 7; u++) {
        const int rsrc0 = r0 + 5 * (u - 3);
        for (int v = 0; v < 7; v++) {
            const int t = u * 7 + v;
            __syncthreads();
            for (int e = tid; e < 16 * 28; e += 256) {
                const int i = e / 28, j = e - i * 28;
                const int gr = rsrc0 + i;
                float4 val = make_float4(0.f, 0.f, 0.f, 0.f);
                if (gr >= 0 && gr < HH)
                    val = *(const float4*)&g_yt[(((size_t)b * 49 + t) * HH + gr) * YSTR + j * 4];
                *(float4*)&sy[i][16 + j * 4] = val;
            }
            __syncthreads();
            const int dv = 5 * (v - 3);
#pragma unroll
            for (int o = 0; o < 7; o++) {
                const int e = o * 256 + tid;
                if (e < 16 * HH) {
                    const int rr = e / HH, cc = e - rr * HH;
                    acc[o] += sy[rr][16 + cc + dv];
                }
            }
        }
    }

    const float scale = bg[0] * rsqrtf(bv[0] + 1e-5f);
#pragma unroll
    for (int o = 0; o < 7; o++) {
        const int e = o * 256 + tid;
        if (e < 16 * HH) {
            const int rr = e / HH, cc = e - rr * HH;
            const int gr = r0 + rr;
            if (gr < HH) {
                float y = acc[o] + cb[0];
                y = (y - bm[0]) * scale + bb[0];
                const float gl = 0.5f * y * (1.f + erff(y * 0.70710678118654752f));
                g_imp[b * PIX + gr * HH + cc] = 1.f / (1.f + expf(-gl));
            }
        }
    }
}

// ---------------------------------------------------------------------------
// 3) top-K per batch: radix-256 threshold + ballot compaction, 1024 threads.
// ---------------------------------------------------------------------------
#define NCHK ((PIX + 255) / 256)   // 48
#define TKT  1024

__global__ __launch_bounds__(TKT) void topk_kernel()
{
    extern __shared__ unsigned sbits[];     // [PIX]
    __shared__ int hist[256];
    __shared__ int cgt[NCHK], ceq[NCHK];
    __shared__ unsigned sh_prefix;
    __shared__ int sh_above;

    const int b    = blockIdx.x;
    const int tid  = threadIdx.x;
    const int lane = tid & 31;
    const int wrp  = tid >> 5;              // 0..31
    const float* v = g_imp + b * PIX;

    for (int i = tid; i < PIX; i += TKT)
        sbits[i] = __float_as_uint(v[i]);
    __syncthreads();

    unsigned prefix = 0;
    int kneed = KTOK;

#pragma unroll
    for (int shift = 24; shift >= 0; shift -= 8) {
        if (tid < 256) hist[tid] = 0;
        __syncthreads();
        const unsigned pm = (shift == 24) ? 0u : (0xFFFFFFFFu << (shift + 8));
        for (int i = tid; i < PIX; i += TKT) {
            const unsigned bits = sbits[i];
            if ((bits & pm) == prefix)
                atomicAdd(&hist[(bits >> shift) & 255], 1);
        }
        __syncthreads();
        for (int off = 1; off < 256; off <<= 1) {
            int val = 0;
            if (tid < 256) val = (tid + off < 256) ? hist[tid + off] : 0;
            __syncthreads();
            if (tid < 256) hist[tid] += val;
            __syncthreads();
        }
        if (tid < 256) {
            const int here  = hist[tid];
            const int above = (tid == 255) ? 0 : hist[tid + 1];
            if (here >= kneed && above < kneed) {
                sh_prefix = prefix | ((unsigned)tid << shift);
                sh_above  = above;
            }
        }
        __syncthreads();
        prefix = sh_prefix;
        kneed -= sh_above;
        __syncthreads();
    }

    const unsigned T = prefix;
    const int tn = kneed;                    // ties to take (lowest index first)

    for (int c = wrp; c < NCHK; c += 32) {
        int gt = 0, eq = 0;
#pragma unroll
        for (int g = 0; g < 8; g++) {
            const int i = c * 256 + g * 32 + lane;
            const unsigned bits = (i < PIX) ? sbits[i] : 0u;
            const unsigned bg = __ballot_sync(0xffffffffu, bits > T);
            const unsigned be = __ballot_sync(0xffffffffu, bits == T && i < PIX);
            gt += __popc(bg); eq += __popc(be);
        }
        if (lane == 0) { cgt[c] = gt; ceq[c] = eq; }
    }
    __syncthreads();
    if (tid == 0) {
        int sg = 0, se = 0;
        for (int c = 0; c < NCHK; c++) {
            const int tg2 = cgt[c], te = ceq[c];
            cgt[c] = sg; ceq[c] = se;
            sg += tg2; se += te;
        }
    }
    __syncthreads();

    const unsigned lmask = (1u << lane) - 1u;
    for (int c = wrp; c < NCHK; c += 32) {
        int gt_run = cgt[c], eq_run = ceq[c];
#pragma unroll
        for (int g = 0; g < 8; g++) {
            const int i = c * 256 + g * 32 + lane;
            const unsigned bits = (i < PIX) ? sbits[i] : 0u;
            const bool isgt = bits > T;
            const bool iseq = (bits == T) && (i < PIX);
            const unsigned bg = __ballot_sync(0xffffffffu, isgt);
            const unsigned be = __ballot_sync(0xffffffffu, iseq);
            const int gt_before = gt_run + __popc(bg & lmask);
            const int eq_before = eq_run + __popc(be & lmask);
            if (isgt)
                g_idx[b * KTOK + gt_before + min(eq_before, tn)] = i;
            else if (iseq && eq_before < tn)
                g_idx[b * KTOK + gt_before + eq_before] = i;
            gt_run += __popc(bg);
            eq_run += __popc(be);
        }
    }
}

// ---------------------------------------------------------------------------
// 4) positional-encoding frequency table
// ---------------------------------------------------------------------------
__global__ void freq_kernel()
{
    const int i = threadIdx.x;           // 64
    const float cst = (float)(-(log(10000.0) / 128.0));
    const float a = (float)(2 * i) * cst;
    g_freq[i] = (float)exp((double)a);
}

// ---------------------------------------------------------------------------
// 5) gather tokens: tokens[b,k,c] = x[b,c,p]*imp[b,p] + PE[p,c]
// ---------------------------------------------------------------------------
__global__ void gather_kernel(const float* __restrict__ x)
{
    const int b = blockIdx.y, k = blockIdx.x, c = threadIdx.x;
    const int p = g_idx[b * KTOK + k];
    const float val = x[((size_t)b * CCH + c) * PIX + p] * g_imp[b * PIX + p];
    const float arg = (float)p * g_freq[c >> 1];
    const float pe  = (c & 1) ? cosf(arg) : sinf(arg);
    g_tokens[((size_t)b * KTOK + k) * CCH + c] = val + pe;
}

// ---------------------------------------------------------------------------
// 6) tf32 tensor-core GEMM: C[m,n] = act( sum_k A[m,k]*B[n,k] + bias[n] )
// ---------------------------------------------------------------------------
template <bool RELU>
__global__ __launch_bounds__(256) void gemm_tf32(
    const float* __restrict__ A, const float* __restrict__ B,
    const float* __restrict__ bias, float* __restrict__ C,
    int M, int N, int K)
{
    __shared__ unsigned As[128][33];
    __shared__ unsigned Bs[64][33];

    const int tid  = threadIdx.x;
    const int lane = tid & 31;
    const int wid  = tid >> 5;
    const int wm   = wid >> 1;
    const int wn   = wid & 1;
    const int g    = lane >> 2;
    const int tg   = lane & 3;
    const int bm   = blockIdx.y * 128, bn = blockIdx.x * 64;

    float acc[2][4][4];
#pragma unroll
    for (int mi = 0; mi < 2; mi++)
#pragma unroll
        for (int ni = 0; ni < 4; ni++)
#pragma unroll
            for (int e = 0; e < 4; e++) acc[mi][ni][e] = 0.f;

    for (int k0 = 0; k0 < K; k0 += 32) {
#pragma unroll
        for (int i = 0; i < 4; i++) {
            const int f = tid + i * 256;
            const int row = f >> 3, c4 = (f & 7) * 4;
            const float4 v = *(const float4*)&A[(size_t)(bm + row) * K + k0 + c4];
            As[row][c4 + 0] = tf32_of(v.x); As[row][c4 + 1] = tf32_of(v.y);
            As[row][c4 + 2] = tf32_of(v.z); As[row][c4 + 3] = tf32_of(v.w);
        }
#pragma unroll
        for (int i = 0; i < 2; i++) {
            const int f = tid + i * 256;
            const int row = f >> 3, c4 = (f & 7) * 4;
            const float4 v = *(const float4*)&B[(size_t)(bn + row) * K + k0 + c4];
            Bs[row][c4 + 0] = tf32_of(v.x); Bs[row][c4 + 1] = tf32_of(v.y);
            Bs[row][c4 + 2] = tf32_of(v.z); Bs[row][c4 + 3] = tf32_of(v.w);
        }
        __syncthreads();

#pragma unroll
        for (int ks = 0; ks < 4; ks++) {
            const int kb = ks * 8;
            unsigned a[2][4], bf[4][2];
#pragma unroll
            for (int mi = 0; mi < 2; mi++) {
                const int r0 = wm * 32 + mi * 16 + g;
                a[mi][0] = As[r0][kb + tg];
                a[mi][1] = As[r0 + 8][kb + tg];
                a[mi][2] = As[r0][kb + tg + 4];
                a[mi][3] = As[r0 + 8][kb + tg + 4];
            }
#pragma unroll
            for (int ni = 0; ni < 4; ni++) {
                const int n0 = wn * 32 + ni * 8 + g;
                bf[ni][0] = Bs[n0][kb + tg];
                bf[ni][1] = Bs[n0][kb + tg + 4];
            }
#pragma unroll
            for (int mi = 0; mi < 2; mi++)
#pragma unroll
                for (int ni = 0; ni < 4; ni++)
                    mma_tf32(acc[mi][ni], a[mi], bf[ni]);
        }
        __syncthreads();
    }

#pragma unroll
    for (int mi = 0; mi < 2; mi++) {
        const int r0 = bm + wm * 32 + mi * 16 + g;
#pragma unroll
        for (int ni = 0; ni < 4; ni++) {
            const int c0 = bn + wn * 32 + ni * 8 + tg * 2;
            const float b0 = bias[c0], b1 = bias[c0 + 1];
            float2 v0 = { acc[mi][ni][0] + b0, acc[mi][ni][1] + b1 };
            float2 v1 = { acc[mi][ni][2] + b0, acc[mi][ni][3] + b1 };
            if (RELU) {
                v0.x = fmaxf(v0.x, 0.f); v0.y = fmaxf(v0.y, 0.f);
                v1.x = fmaxf(v1.x, 0.f); v1.y = fmaxf(v1.y, 0.f);
            }
            *(float2*)&C[(size_t)r0 * N + c0]       = v0;
            *(float2*)&C[(size_t)(r0 + 8) * N + c0] = v1;
        }
    }
}

// ---------------------------------------------------------------------------
// 7) tensor-core flash attention (one block per (b,h), 512 threads = 16 warps)
// ---------------------------------------------------------------------------
__global__ __launch_bounds__(512) void attn_kernel()
{
    __shared__ unsigned sK[256][18];
    __shared__ unsigned sV[256][24];

    const int h = blockIdx.x, b = blockIdx.y;
    const int tid  = threadIdx.x;
    const int lane = tid & 31;
    const int w    = tid >> 5;
    const int g    = lane >> 2;
    const int tg   = lane & 3;
    const float* qkv = g_qkv + (size_t)b * KTOK * 384;

    unsigned qa[3][8];
#pragma unroll
    for (int qt = 0; qt < 3; qt++) {
        const int row = w * 48 + qt * 16 + g;
        const float* q0 = qkv + (size_t)row * 384 + h * 16;
        const float* q8 = q0 + 8 * 384;
        qa[qt][0] = tf32_of(q0[tg]      * 0.25f);
        qa[qt][1] = tf32_of(q8[tg]      * 0.25f);
        qa[qt][2] = tf32_of(q0[tg + 4]  * 0.25f);
        qa[qt][3] = tf32_of(q8[tg + 4]  * 0.25f);
        qa[qt][4] = tf32_of(q0[tg + 8]  * 0.25f);
        qa[qt][5] = tf32_of(q8[tg + 8]  * 0.25f);
        qa[qt][6] = tf32_of(q0[tg + 12] * 0.25f);
        qa[qt][7] = tf32_of(q8[tg + 12] * 0.25f);
    }

    float m[3][2], l[3][2], o[3][2][4];
#pragma unroll
    for (int qt = 0; qt < 3; qt++) {
        m[qt][0] = m[qt][1] = -1e30f;
        l[qt][0] = l[qt][1] = 0.f;
#pragma unroll
        for (int n = 0; n < 2; n++)
#pragma unroll
            for (int e = 0; e < 4; e++) o[qt][n][e] = 0.f;
    }

    const int src0 = (lane & 28) | (tg >> 1);
    const int src2 = src0 + 2;

    for (int ch = 0; ch < 3; ch++) {
        __syncthreads();
        for (int e = tid; e < 256 * 16; e += 512) {
            const int j = e >> 4, d = e & 15;
            const size_t base = (size_t)(ch * 256 + j) * 384 + h * 16 + d;
            sK[j][d] = tf32_of(qkv[base + 128]);
            sV[j][d] = tf32_of(qkv[base + 256]);
        }
        __syncthreads();

        for (int sub = 0; sub < 8; sub++) {
            unsigned kb[4][2][2];
#pragma unroll
            for (int t = 0; t < 4; t++) {
                const int key = sub * 32 + t * 8 + g;
                kb[t][0][0] = sK[key][tg];
                kb[t][0][1] = sK[key][tg + 4];
                kb[t][1][0] = sK[key][tg + 8];
                kb[t][1][1] = sK[key][tg + 12];
            }
#pragma unroll
            for (int qt = 0; qt < 3; qt++) {
                float s[4][4];
#pragma unroll
                for (int t = 0; t < 4; t++) {
                    s[t][0] = s[t][1] = s[t][2] = s[t][3] = 0.f;
                    mma_tf32(s[t], qa[qt],     kb[t][0]);
                    mma_tf32(s[t], qa[qt] + 4, kb[t][1]);
                }
                float mx0 = s[0][0], mx1 = s[0][2];
#pragma unroll
                for (int t = 0; t < 4; t++) {
                    mx0 = fmaxf(mx0, fmaxf(s[t][0], s[t][1]));
                    mx1 = fmaxf(mx1, fmaxf(s[t][2], s[t][3]));
                }
                mx0 = fmaxf(mx0, __shfl_xor_sync(0xffffffffu, mx0, 1));
                mx0 = fmaxf(mx0, __shfl_xor_sync(0xffffffffu, mx0, 2));
                mx1 = fmaxf(mx1, __shfl_xor_sync(0xffffffffu, mx1, 1));
                mx1 = fmaxf(mx1, __shfl_xor_sync(0xffffffffu, mx1, 2));
                const float nm0 = fmaxf(m[qt][0], mx0);
                const float nm1 = fmaxf(m[qt][1], mx1);
                const float f0 = __expf(m[qt][0] - nm0);
                const float f1 = __expf(m[qt][1] - nm1);
                m[qt][0] = nm0; m[qt][1] = nm1;
                float s0 = 0.f, s1 = 0.f;
#pragma unroll
                for (int t = 0; t < 4; t++) {
                    s[t][0] = tf32f(__expf(s[t][0] - nm0));
                    s[t][1] = tf32f(__expf(s[t][1] - nm0));
                    s[t][2] = tf32f(__expf(s[t][2] - nm1));
                    s[t][3] = tf32f(__expf(s[t][3] - nm1));
                    s0 += s[t][0] + s[t][1];
                    s1 += s[t][2] + s[t][3];
                }
                l[qt][0] = l[qt][0] * f0 + s0;
                l[qt][1] = l[qt][1] * f1 + s1;
#pragma unroll
                for (int n = 0; n < 2; n++) {
                    o[qt][n][0] *= f0; o[qt][n][1] *= f0;
                    o[qt][n][2] *= f1; o[qt][n][3] *= f1;
                }
#pragma unroll
                for (int t = 0; t < 4; t++) {
                    unsigned a[4];
                    {
                        const float t00 = __shfl_sync(0xffffffffu, s[t][0], src0);
                        const float t01 = __shfl_sync(0xffffffffu, s[t][1], src0);
                        const float t10 = __shfl_sync(0xffffffffu, s[t][2], src0);
                        const float t11 = __shfl_sync(0xffffffffu, s[t][3], src0);
                        a[0] = __float_as_uint((tg & 1) ? t01 : t00);
                        a[1] = __float_as_uint((tg & 1) ? t11 : t10);
                        const float u00 = __shfl_sync(0xffffffffu, s[t][0], src2);
                        const float u01 = __shfl_sync(0xffffffffu, s[t][1], src2);
                        const float u10 = __shfl_sync(0xffffffffu, s[t][2], src2);
                        const float u11 = __shfl_sync(0xffffffffu, s[t][3], src2);
                        a[2] = __float_as_uint((tg & 1) ? u01 : u00);
                        a[3] = __float_as_uint((tg & 1) ? u11 : u10);
                    }
                    const int key = sub * 32 + t * 8;
                    unsigned vb0[2], vb1[2];
                    vb0[0] = sV[key + tg][g];         vb0[1] = sV[key + tg + 4][g];
                    vb1[0] = sV[key + tg][g + 8];     vb1[1] = sV[key + tg + 4][g + 8];
                    mma_tf32(o[qt][0], a, vb0);
                    mma_tf32(o[qt][1], a, vb1);
                }
            }
        }
    }

#pragma unroll
    for (int qt = 0; qt < 3; qt++) {
        float l0 = l[qt][0], l1 = l[qt][1];
        l0 += __shfl_xor_sync(0xffffffffu, l0, 1);
        l0 += __shfl_xor_sync(0xffffffffu, l0, 2);
        l1 += __shfl_xor_sync(0xffffffffu, l1, 1);
        l1 += __shfl_xor_sync(0xffffffffu, l1, 2);
        const float inv0 = 1.f / l0, inv1 = 1.f / l1;
        const int row = w * 48 + qt * 16 + g;
        float* out0 = g_attn + ((size_t)b * KTOK + row) * CCH + h * 16 + tg * 2;
        float* out8 = out0 + 8 * CCH;
#pragma unroll
        for (int n = 0; n < 2; n++) {
            *(float2*)(out0 + n * 8) = make_float2(o[qt][n][0] * inv0, o[qt][n][1] * inv0);
            *(float2*)(out8 + n * 8) = make_float2(o[qt][n][2] * inv1, o[qt][n][3] * inv1);
        }
    }
}

// ---------------------------------------------------------------------------
// 8) residual + LayerNorm
// ---------------------------------------------------------------------------
__global__ void ln_kernel(const float* __restrict__ a, const float* __restrict__ r,
                          const float* __restrict__ g, const float* __restrict__ be,
                          float* __restrict__ out)
{
    const int row  = blockIdx.x * 8 + (threadIdx.x >> 5);
    const int lane = threadIdx.x & 31;
    const float4 va = ((const float4*)(a + (size_t)row * CCH))[lane];
    const float4 vr = ((const float4*)(r + (size_t)row * CCH))[lane];
    float4 t;
    t.x = va.x + vr.x; t.y = va.y + vr.y; t.z = va.z + vr.z; t.w = va.w + vr.w;
    float s  = t.x + t.y + t.z + t.w;
    float s2 = t.x*t.x + t.y*t.y + t.z*t.z + t.w*t.w;
#pragma unroll
    for (int o = 16; o > 0; o >>= 1) {
        s  += __shfl_xor_sync(0xffffffffu, s,  o);
        s2 += __shfl_xor_sync(0xffffffffu, s2, o);
    }
    const float mu  = s * (1.f / 128.f);
    const float var = s2 * (1.f / 128.f) - mu * mu;
    const float inv = rsqrtf(var + 1e-5f);
    const float4 gv = ((const float4*)g)[lane];
    const float4 bv = ((const float4*)be)[lane];
    float4 o;
    o.x = (t.x - mu) * inv * gv.x + bv.x;
    o.y = (t.y - mu) * inv * gv.y + bv.y;
    o.z = (t.z - mu) * inv * gv.z + bv.z;
    o.w = (t.w - mu) * inv * gv.w + bv.w;
    ((float4*)(out + (size_t)row * CCH))[lane] = o;
}

// ---------------------------------------------------------------------------
// 9) out = x * imp (everywhere), then scatter t2 at selected pixels
// ---------------------------------------------------------------------------
__global__ void xs_kernel(const float* __restrict__ x, float* __restrict__ out)
{
    const unsigned i = blockIdx.x * 256u + threadIdx.x;
    const unsigned total = (unsigned)BATCH * CCH * (PIX / 4);
    if (i >= total) return;
    const unsigned base = i * 4u;
    const unsigned p4 = base % PIX;
    const unsigned b  = (base / PIX) / CCH;
    const float4 xv = *(const float4*)(x + base);
    const float* ip = g_imp + (size_t)b * PIX + p4;
    float4 o;
    o.x = xv.x * ip[0]; o.y = xv.y * ip[1]; o.z = xv.z * ip[2]; o.w = xv.w * ip[3];
    *(float4*)(out + base) = o;
}

__global__ void scatter_kernel(float* __restrict__ out)
{
    const int b = blockIdx.y, k = blockIdx.x, c = threadIdx.x;
    const int p = g_idx[b * KTOK + k];
    out[((size_t)b * CCH + c) * PIX + p] = g_t2[((size_t)b * KTOK + k) * CCH + c];
}

// ---------------------------------------------------------------------------
// launch
// ---------------------------------------------------------------------------
extern "C" void kernel_launch(void* const* d_in, const int* in_sizes, int n_in,
                              void* d_out, int out_size)
{
    const float* x      = (const float*)d_in[0];
    const float* conv_w = (const float*)d_in[1];
    const float* conv_b = (const float*)d_in[2];
    const float* bn_g   = (const float*)d_in[3];
    const float* bn_b   = (const float*)d_in[4];
    const float* bn_m   = (const float*)d_in[5];
    const float* bn_v   = (const float*)d_in[6];
    const float* w_qkv  = (const float*)d_in[7];
    const float* b_qkv  = (const float*)d_in[8];
    const float* w_o    = (const float*)d_in[9];
    const float* b_o    = (const float*)d_in[10];
    const float* ln1_g  = (const float*)d_in[11];
    const float* ln1_b  = (const float*)d_in[12];
    const float* w1     = (const float*)d_in[13];
    const float* b1     = (const float*)d_in[14];
    const float* w2     = (const float*)d_in[15];
    const float* b2     = (const float*)d_in[16];
    const float* ln2_g  = (const float*)d_in[17];
    const float* ln2_b  = (const float*)d_in[18];
    float* out = (float*)d_out;

    float *p_tokens, *p_qkv, *p_attn, *p_t1, *p_h1, *p_tmp, *p_t2;
    cudaGetSymbolAddress((void**)&p_tokens, g_tokens);
    cudaGetSymbolAddress((void**)&p_qkv,    g_qkv);
    cudaGetSymbolAddress((void**)&p_attn,   g_attn);
    cudaGetSymbolAddress((void**)&p_t1,     g_t1);
    cudaGetSymbolAddress((void**)&p_h1,     g_h1);
    cudaGetSymbolAddress((void**)&p_tmp,    g_tmp);
    cudaGetSymbolAddress((void**)&p_t2,     g_t2);

    const int convgemm_smem = (64 * 132 + 32 * 132) * (int)sizeof(float);
    cudaFuncSetAttribute(convgemm_kernel, cudaFuncAttributeMaxDynamicSharedMemorySize,
                         convgemm_smem);
    cudaFuncSetAttribute(topk_kernel, cudaFuncAttributeMaxDynamicSharedMemorySize,
                         PIX * (int)sizeof(unsigned));

    // conv (tensor-core GEMM + shift-add/activation) -> top-K -> tokens
    freq_kernel<<<1, 64>>>();
    convgemm_kernel<<<dim3(NPT, BATCH), 256, convgemm_smem>>>(x, conv_w);
    convadd_kernel<<<dim3(7, BATCH), 256>>>(conv_b, bn_g, bn_b, bn_m, bn_v);
    topk_kernel<<<BATCH, TKT, PIX * sizeof(unsigned)>>>();
    gather_kernel<<<dim3(KTOK, BATCH), CCH>>>(x);

    // transformer encoder layer (tf32 tensor cores throughout)
    gemm_tf32<false><<<dim3(384 / 64, NTOK / 128), 256>>>(p_tokens, w_qkv, b_qkv, p_qkv, NTOK, 384, 128);

    attn_kernel<<<dim3(NHEAD, BATCH), 512>>>();

    gemm_tf32<false><<<dim3(128 / 64, NTOK / 128), 256>>>(p_attn, w_o, b_o, p_tmp, NTOK, 128, 128);
    ln_kernel<<<NTOK / 8, 256>>>(p_tokens, p_tmp, ln1_g, ln1_b, p_t1);
    gemm_tf32<true ><<<dim3(256 / 64, NTOK / 128), 256>>>(p_t1, w1, b1, p_h1, NTOK, 256, 128);
    gemm_tf32<false><<<dim3(128 / 64, NTOK / 128), 256>>>(p_h1, w2, b2, p_tmp, NTOK, 128, 256);
    ln_kernel<<<NTOK / 8, 256>>>(p_t1, p_tmp, ln2_g, ln2_b, p_t2);

    // assemble output
    xs_kernel<<<(BATCH * CCH * (PIX / 4) + 255) / 256, 256>>>(x, out);
    scatter_kernel<<<dim3(KTOK, BATCH), CCH>>>(out);
}

// round 7
// speedup vs baseline: 1.4453x; 1.0193x over previous
#include <cuda_runtime.h>
#include <cuda_bf16.h>
#include <math.h>

// ---------------------------------------------------------------------------
// Problem constants
// ---------------------------------------------------------------------------
#define BATCH 32
#define CCH   128           // channels / d_model
#define HH    110           // spatial
#define PIX   (HH*HH)       // 12100
#define KTOK  768
#define NHEAD 8
#define HD    16
#define NTOK  (BATCH*KTOK)  // 24576
#define YSTR  112           // padded row stride for y maps (16B-aligned rows)
#define CNT   128           // conv GEMM pixel tile
#define NPT   ((PIX + CNT - 1) / CNT)   // 95

typedef unsigned long long u64;

// ---------------------------------------------------------------------------
// helpers
// ---------------------------------------------------------------------------
__device__ __forceinline__ unsigned tf32_of(float x) {
    unsigned r; asm("cvt.rna.tf32.f32 %0, %1;" : "=r"(r) : "f"(x)); return r;
}
__device__ __forceinline__ float tf32f(float x) {
    return __uint_as_float(tf32_of(x));
}
__device__ __forceinline__ void split_tf32(float v, unsigned &hi, unsigned &lo) {
    hi = tf32_of(v);
    lo = tf32_of(v - __uint_as_float(hi));
}
__device__ __forceinline__ void mma_tf32(float* c, const unsigned* a, const unsigned* b) {
    asm("mma.sync.aligned.m16n8k8.row.col.f32.tf32.tf32.f32 "
        "{%0,%1,%2,%3},{%4,%5,%6,%7},{%8,%9},{%0,%1,%2,%3};"
        : "+f"(c[0]), "+f"(c[1]), "+f"(c[2]), "+f"(c[3])
        : "r"(a[0]), "r"(a[1]), "r"(a[2]), "r"(a[3]), "r"(b[0]), "r"(b[1]));
}

// ---------------------------------------------------------------------------
// Scratch (static device globals; no allocation allowed)
// ---------------------------------------------------------------------------
__device__ float g_yt[(size_t)BATCH*49*HH*YSTR];  // per-tap channel-reduced maps
__device__ float g_imp[BATCH*PIX];                // importance map
__device__ int   g_idx[BATCH*KTOK];               // selected (sorted) pixel indices
__device__ float g_freq[64];                      // positional-encoding frequencies
__device__ float g_tokens[NTOK*CCH];
__device__ float g_qkv[NTOK*3*CCH];
__device__ float g_attn[NTOK*CCH];
__device__ float g_t1[NTOK*CCH];
__device__ float g_h1[NTOK*2*CCH];
__device__ float g_tmp[NTOK*CCH];
__device__ float g_t2[NTOK*CCH];

// ---------------------------------------------------------------------------
// 1a) conv as GEMM (3xTF32, fp32-accurate): Y[t][p] = sum_c W[t][c] X[c][p].
//     Splits hoisted to smem load time (Ah/Al once, Bh/Bl per K-chunk).
//     grid (95 pixel-tiles, 32 batch), 256 threads (8 warps as 2m x 4n).
// ---------------------------------------------------------------------------
__global__ __launch_bounds__(256) void convgemm_kernel(
    const float* __restrict__ x, const float* __restrict__ w)
{
    extern __shared__ unsigned csm[];
    unsigned (*Ah)[132] = (unsigned(*)[132])csm;            // 64 x 132
    unsigned (*Al)[132] = Ah + 64;
    unsigned (*Bh)[132] = Al + 64;                          // 32 x 132
    unsigned (*Bl)[132] = Bh + 32;

    const int pt = blockIdx.x, b = blockIdx.y;
    const int p0 = pt * CNT;
    const int tid = threadIdx.x, lane = tid & 31, wid = tid >> 5;
    const int wm = wid >> 2, wn = wid & 3;
    const int g = lane >> 2, tg = lane & 3;

    // A = W^T split once: rows 49..63 zero
    for (int e = tid; e < 64 * 128; e += 256) {
        const int t = e & 63, c = e >> 6;
        const float v = (t < 49) ? w[c * 49 + t] : 0.f;
        split_tf32(v, Ah[t][c], Al[t][c]);
    }

    float acc[2][4][4];
#pragma unroll
    for (int mi = 0; mi < 2; mi++)
#pragma unroll
        for (int ni = 0; ni < 4; ni++)
#pragma unroll
            for (int e = 0; e < 4; e++) acc[mi][ni][e] = 0.f;

    for (int k0 = 0; k0 < 128; k0 += 32) {
        __syncthreads();
        for (int e = tid; e < 32 * 128; e += 256) {
            const int c = e >> 7, p = e & 127;
            const int gp = p0 + p;
            const float v = (gp < PIX) ? x[((size_t)b * CCH + k0 + c) * PIX + gp] : 0.f;
            split_tf32(v, Bh[c][p], Bl[c][p]);
        }
        __syncthreads();
#pragma unroll
        for (int ks = 0; ks < 4; ks++) {
            const int kk = k0 + ks * 8 + tg;   // absolute k into A
            const int kb = ks * 8 + tg;        // local k into B
            unsigned ah[2][4], al[2][4];
#pragma unroll
            for (int mi = 0; mi < 2; mi++) {
                const int rr = wm * 32 + mi * 16 + g;
                ah[mi][0] = Ah[rr][kk];      al[mi][0] = Al[rr][kk];
                ah[mi][1] = Ah[rr + 8][kk];  al[mi][1] = Al[rr + 8][kk];
                ah[mi][2] = Ah[rr][kk + 4];  al[mi][2] = Al[rr][kk + 4];
                ah[mi][3] = Ah[rr + 8][kk+4];al[mi][3] = Al[rr + 8][kk+4];
            }
#pragma unroll
            for (int ni = 0; ni < 4; ni++) {
                const int n0 = wn * 32 + ni * 8 + g;
                unsigned bh[2], bl[2];
                bh[0] = Bh[kb][n0];     bl[0] = Bl[kb][n0];
                bh[1] = Bh[kb + 4][n0]; bl[1] = Bl[kb + 4][n0];
#pragma unroll
                for (int mi = 0; mi < 2; mi++) {
                    mma_tf32(acc[mi][ni], ah[mi], bh);   // hi*hi
                    mma_tf32(acc[mi][ni], al[mi], bh);   // lo*hi
                    mma_tf32(acc[mi][ni], ah[mi], bl);   // hi*lo
                }
            }
        }
    }

    // store into padded [b][t][r][0..111] layout
#pragma unroll
    for (int mi = 0; mi < 2; mi++) {
        const int t = wm * 32 + mi * 16 + g;
#pragma unroll
        for (int ni = 0; ni < 4; ni++) {
            const int pcol = p0 + wn * 32 + ni * 8 + tg * 2;
            if (pcol < PIX) {
                const int r0r = pcol / HH, c0r = pcol - r0r * HH;
                const bool ok1 = (pcol + 1 < PIX);
                const int r1r = (pcol + 1) / HH, c1r = (pcol + 1) - r1r * HH;
                if (t < 49) {
                    float* yb = g_yt + ((size_t)b * 49 + t) * HH * YSTR;
                    yb[r0r * YSTR + c0r] = acc[mi][ni][0];
                    if (ok1) yb[r1r * YSTR + c1r] = acc[mi][ni][1];
                }
                if (t + 8 < 49) {
                    float* yb = g_yt + ((size_t)b * 49 + t + 8) * HH * YSTR;
                    yb[r0r * YSTR + c0r] = acc[mi][ni][2];
                    if (ok1) yb[r1r * YSTR + c1r] = acc[mi][ni][3];
                }
            }
        }
    }
}

// ---------------------------------------------------------------------------
// 1b) shift-add over 49 taps + BN + GELU + sigmoid, one thread per pixel.
//     49 predicated coalesced loads, full MLP, no syncs.
// ---------------------------------------------------------------------------
__global__ void convadd_kernel(
    const float* __restrict__ cb, const float* __restrict__ bg,
    const float* __restrict__ bb, const float* __restrict__ bm,
    const float* __restrict__ bv)
{
    const int idx = blockIdx.x * 256 + threadIdx.x;
    if (idx >= BATCH * PIX) return;
    const int b = idx / PIX, p = idx - b * PIX;
    const int r = p / HH, c = p - r * HH;
    const float* yb = g_yt + (size_t)b * 49 * HH * YSTR;

    float a = 0.f;
#pragma unroll
    for (int u = 0; u < 7; u++) {
        const int sr = r + 5 * (u - 3);
        if (sr < 0 || sr >= HH) continue;
#pragma unroll
        for (int v = 0; v < 7; v++) {
            const int sc = c + 5 * (v - 3);
            if (sc >= 0 && sc < HH)
                a += yb[((u * 7 + v) * HH + sr) * YSTR + sc];
        }
    }

    const float scale = bg[0] * rsqrtf(bv[0] + 1e-5f);
    float y = a + cb[0];
    y = (y - bm[0]) * scale + bb[0];
    const float gl = 0.5f * y * (1.f + erff(y * 0.70710678118654752f));
    g_imp[idx] = 1.f / (1.f + expf(-gl));
}

// ---------------------------------------------------------------------------
// 3) top-K per batch: radix-256 threshold + ballot compaction, 1024 threads.
// ---------------------------------------------------------------------------
#define NCHK ((PIX + 255) / 256)   // 48
#define TKT  1024

__global__ __launch_bounds__(TKT) void topk_kernel()
{
    extern __shared__ unsigned sbits[];     // [PIX]
    __shared__ int hist[256];
    __shared__ int cgt[NCHK], ceq[NCHK];
    __shared__ unsigned sh_prefix;
    __shared__ int sh_above;

    const int b    = blockIdx.x;
    const int tid  = threadIdx.x;
    const int lane = tid & 31;
    const int wrp  = tid >> 5;              // 0..31
    const float* v = g_imp + b * PIX;

    for (int i = tid; i < PIX; i += TKT)
        sbits[i] = __float_as_uint(v[i]);
    __syncthreads();

    unsigned prefix = 0;
    int kneed = KTOK;

#pragma unroll
    for (int shift = 24; shift >= 0; shift -= 8) {
        if (tid < 256) hist[tid] = 0;
        __syncthreads();
        const unsigned pm = (shift == 24) ? 0u : (0xFFFFFFFFu << (shift + 8));
        for (int i = tid; i < PIX; i += TKT) {
            const unsigned bits = sbits[i];
            if ((bits & pm) == prefix)
                atomicAdd(&hist[(bits >> shift) & 255], 1);
        }
        __syncthreads();
        for (int off = 1; off < 256; off <<= 1) {
            int val = 0;
            if (tid < 256) val = (tid + off < 256) ? hist[tid + off] : 0;
            __syncthreads();
            if (tid < 256) hist[tid] += val;
            __syncthreads();
        }
        if (tid < 256) {
            const int here  = hist[tid];
            const int above = (tid == 255) ? 0 : hist[tid + 1];
            if (here >= kneed && above < kneed) {
                sh_prefix = prefix | ((unsigned)tid << shift);
                sh_above  = above;
            }
        }
        __syncthreads();
        prefix = sh_prefix;
        kneed -= sh_above;
        __syncthreads();
    }

    const unsigned T = prefix;
    const int tn = kneed;                    // ties to take (lowest index first)

    for (int c = wrp; c < NCHK; c += 32) {
        int gt = 0, eq = 0;
#pragma unroll
        for (int g = 0; g < 8; g++) {
            const int i = c * 256 + g * 32 + lane;
            const unsigned bits = (i < PIX) ? sbits[i] : 0u;
            const unsigned bg = __ballot_sync(0xffffffffu, bits > T);
            const unsigned be = __ballot_sync(0xffffffffu, bits == T && i < PIX);
            gt += __popc(bg); eq += __popc(be);
        }
        if (lane == 0) { cgt[c] = gt; ceq[c] = eq; }
    }
    __syncthreads();
    if (tid == 0) {
        int sg = 0, se = 0;
        for (int c = 0; c < NCHK; c++) {
            const int tg2 = cgt[c], te = ceq[c];
            cgt[c] = sg; ceq[c] = se;
            sg += tg2; se += te;
        }
    }
    __syncthreads();

    const unsigned lmask = (1u << lane) - 1u;
    for (int c = wrp; c < NCHK; c += 32) {
        int gt_run = cgt[c], eq_run = ceq[c];
#pragma unroll
        for (int g = 0; g < 8; g++) {
            const int i = c * 256 + g * 32 + lane;
            const unsigned bits = (i < PIX) ? sbits[i] : 0u;
            const bool isgt = bits > T;
            const bool iseq = (bits == T) && (i < PIX);
            const unsigned bg = __ballot_sync(0xffffffffu, isgt);
            const unsigned be = __ballot_sync(0xffffffffu, iseq);
            const int gt_before = gt_run + __popc(bg & lmask);
            const int eq_before = eq_run + __popc(be & lmask);
            if (isgt)
                g_idx[b * KTOK + gt_before + min(eq_before, tn)] = i;
            else if (iseq && eq_before < tn)
                g_idx[b * KTOK + gt_before + eq_before] = i;
            gt_run += __popc(bg);
            eq_run += __popc(be);
        }
    }
}

// ---------------------------------------------------------------------------
// 4) positional-encoding frequency table
// ---------------------------------------------------------------------------
__global__ void freq_kernel()
{
    const int i = threadIdx.x;           // 64
    const float cst = (float)(-(log(10000.0) / 128.0));
    const float a = (float)(2 * i) * cst;
    g_freq[i] = (float)exp((double)a);
}

// ---------------------------------------------------------------------------
// 5) gather tokens: tokens[b,k,c] = x[b,c,p]*imp[b,p] + PE[p,c]
// ---------------------------------------------------------------------------
__global__ void gather_kernel(const float* __restrict__ x)
{
    const int b = blockIdx.y, k = blockIdx.x, c = threadIdx.x;
    const int p = g_idx[b * KTOK + k];
    const float val = x[((size_t)b * CCH + c) * PIX + p] * g_imp[b * PIX + p];
    const float arg = (float)p * g_freq[c >> 1];
    const float pe  = (c & 1) ? cosf(arg) : sinf(arg);
    g_tokens[((size_t)b * KTOK + k) * CCH + c] = val + pe;
}

// ---------------------------------------------------------------------------
// 6) tf32 tensor-core GEMM: C[m,n] = act( sum_k A[m,k]*B[n,k] + bias[n] )
// ---------------------------------------------------------------------------
template <bool RELU>
__global__ __launch_bounds__(256) void gemm_tf32(
    const float* __restrict__ A, const float* __restrict__ B,
    const float* __restrict__ bias, float* __restrict__ C,
    int M, int N, int K)
{
    __shared__ unsigned As[128][33];
    __shared__ unsigned Bs[64][33];

    const int tid  = threadIdx.x;
    const int lane = tid & 31;
    const int wid  = tid >> 5;
    const int wm   = wid >> 1;
    const int wn   = wid & 1;
    const int g    = lane >> 2;
    const int tg   = lane & 3;
    const int bm   = blockIdx.y * 128, bn = blockIdx.x * 64;

    float acc[2][4][4];
#pragma unroll
    for (int mi = 0; mi < 2; mi++)
#pragma unroll
        for (int ni = 0; ni < 4; ni++)
#pragma unroll
            for (int e = 0; e < 4; e++) acc[mi][ni][e] = 0.f;

    for (int k0 = 0; k0 < K; k0 += 32) {
#pragma unroll
        for (int i = 0; i < 4; i++) {
            const int f = tid + i * 256;
            const int row = f >> 3, c4 = (f & 7) * 4;
            const float4 v = *(const float4*)&A[(size_t)(bm + row) * K + k0 + c4];
            As[row][c4 + 0] = tf32_of(v.x); As[row][c4 + 1] = tf32_of(v.y);
            As[row][c4 + 2] = tf32_of(v.z); As[row][c4 + 3] = tf32_of(v.w);
        }
#pragma unroll
        for (int i = 0; i < 2; i++) {
            const int f = tid + i * 256;
            const int row = f >> 3, c4 = (f & 7) * 4;
            const float4 v = *(const float4*)&B[(size_t)(bn + row) * K + k0 + c4];
            Bs[row][c4 + 0] = tf32_of(v.x); Bs[row][c4 + 1] = tf32_of(v.y);
            Bs[row][c4 + 2] = tf32_of(v.z); Bs[row][c4 + 3] = tf32_of(v.w);
        }
        __syncthreads();

#pragma unroll
        for (int ks = 0; ks < 4; ks++) {
            const int kb = ks * 8;
            unsigned a[2][4], bf[4][2];
#pragma unroll
            for (int mi = 0; mi < 2; mi++) {
                const int r0 = wm * 32 + mi * 16 + g;
                a[mi][0] = As[r0][kb + tg];
                a[mi][1] = As[r0 + 8][kb + tg];
                a[mi][2] = As[r0][kb + tg + 4];
                a[mi][3] = As[r0 + 8][kb + tg + 4];
            }
#pragma unroll
            for (int ni = 0; ni < 4; ni++) {
                const int n0 = wn * 32 + ni * 8 + g;
                bf[ni][0] = Bs[n0][kb + tg];
                bf[ni][1] = Bs[n0][kb + tg + 4];
            }
#pragma unroll
            for (int mi = 0; mi < 2; mi++)
#pragma unroll
                for (int ni = 0; ni < 4; ni++)
                    mma_tf32(acc[mi][ni], a[mi], bf[ni]);
        }
        __syncthreads();
    }

#pragma unroll
    for (int mi = 0; mi < 2; mi++) {
        const int r0 = bm + wm * 32 + mi * 16 + g;
#pragma unroll
        for (int ni = 0; ni < 4; ni++) {
            const int c0 = bn + wn * 32 + ni * 8 + tg * 2;
            const float b0 = bias[c0], b1 = bias[c0 + 1];
            float2 v0 = { acc[mi][ni][0] + b0, acc[mi][ni][1] + b1 };
            float2 v1 = { acc[mi][ni][2] + b0, acc[mi][ni][3] + b1 };
            if (RELU) {
                v0.x = fmaxf(v0.x, 0.f); v0.y = fmaxf(v0.y, 0.f);
                v1.x = fmaxf(v1.x, 0.f); v1.y = fmaxf(v1.y, 0.f);
            }
            *(float2*)&C[(size_t)r0 * N + c0]       = v0;
            *(float2*)&C[(size_t)(r0 + 8) * N + c0] = v1;
        }
    }
}

// ---------------------------------------------------------------------------
// 7) tensor-core flash attention. grid (NHEAD, BATCH, 2), 256 threads = 8
//    warps; each warp owns 48 query rows of its 384-query half. K/V staged
//    per 256-key chunk as tf32. Doubled block count vs R6 for latency hiding.
// ---------------------------------------------------------------------------
__global__ __launch_bounds__(256) void attn_kernel()
{
    __shared__ unsigned sK[256][18];
    __shared__ unsigned sV[256][24];

    const int h = blockIdx.x, b = blockIdx.y, qh = blockIdx.z;
    const int tid  = threadIdx.x;
    const int lane = tid & 31;
    const int w    = tid >> 5;           // 0..7
    const int g    = lane >> 2;
    const int tg   = lane & 3;
    const float* qkv = g_qkv + (size_t)b * KTOK * 384;
    const int qbase = qh * 384 + w * 48;

    unsigned qa[3][8];
#pragma unroll
    for (int qt = 0; qt < 3; qt++) {
        const int row = qbase + qt * 16 + g;
        const float* q0 = qkv + (size_t)row * 384 + h * 16;
        const float* q8 = q0 + 8 * 384;
        qa[qt][0] = tf32_of(q0[tg]      * 0.25f);
        qa[qt][1] = tf32_of(q8[tg]      * 0.25f);
        qa[qt][2] = tf32_of(q0[tg + 4]  * 0.25f);
        qa[qt][3] = tf32_of(q8[tg + 4]  * 0.25f);
        qa[qt][4] = tf32_of(q0[tg + 8]  * 0.25f);
        qa[qt][5] = tf32_of(q8[tg + 8]  * 0.25f);
        qa[qt][6] = tf32_of(q0[tg + 12] * 0.25f);
        qa[qt][7] = tf32_of(q8[tg + 12] * 0.25f);
    }

    float m[3][2], l[3][2], o[3][2][4];
#pragma unroll
    for (int qt = 0; qt < 3; qt++) {
        m[qt][0] = m[qt][1] = -1e30f;
        l[qt][0] = l[qt][1] = 0.f;
#pragma unroll
        for (int n = 0; n < 2; n++)
#pragma unroll
            for (int e = 0; e < 4; e++) o[qt][n][e] = 0.f;
    }

    const int src0 = (lane & 28) | (tg >> 1);
    const int src2 = src0 + 2;

    for (int ch = 0; ch < 3; ch++) {
        __syncthreads();
        for (int e = tid; e < 256 * 16; e += 256) {
            const int j = e >> 4, d = e & 15;
            const size_t base = (size_t)(ch * 256 + j) * 384 + h * 16 + d;
            sK[j][d] = tf32_of(qkv[base + 128]);
            sV[j][d] = tf32_of(qkv[base + 256]);
        }
        __syncthreads();

        for (int sub = 0; sub < 8; sub++) {
            unsigned kb[4][2][2];
#pragma unroll
            for (int t = 0; t < 4; t++) {
                const int key = sub * 32 + t * 8 + g;
                kb[t][0][0] = sK[key][tg];
                kb[t][0][1] = sK[key][tg + 4];
                kb[t][1][0] = sK[key][tg + 8];
                kb[t][1][1] = sK[key][tg + 12];
            }
#pragma unroll
            for (int qt = 0; qt < 3; qt++) {
                float s[4][4];
#pragma unroll
                for (int t = 0; t < 4; t++) {
                    s[t][0] = s[t][1] = s[t][2] = s[t][3] = 0.f;
                    mma_tf32(s[t], qa[qt],     kb[t][0]);
                    mma_tf32(s[t], qa[qt] + 4, kb[t][1]);
                }
                float mx0 = s[0][0], mx1 = s[0][2];
#pragma unroll
                for (int t = 0; t < 4; t++) {
                    mx0 = fmaxf(mx0, fmaxf(s[t][0], s[t][1]));
                    mx1 = fmaxf(mx1, fmaxf(s[t][2], s[t][3]));
                }
                mx0 = fmaxf(mx0, __shfl_xor_sync(0xffffffffu, mx0, 1));
                mx0 = fmaxf(mx0, __shfl_xor_sync(0xffffffffu, mx0, 2));
                mx1 = fmaxf(mx1, __shfl_xor_sync(0xffffffffu, mx1, 1));
                mx1 = fmaxf(mx1, __shfl_xor_sync(0xffffffffu, mx1, 2));
                const float nm0 = fmaxf(m[qt][0], mx0);
                const float nm1 = fmaxf(m[qt][1], mx1);
                const float f0 = __expf(m[qt][0] - nm0);
                const float f1 = __expf(m[qt][1] - nm1);
                m[qt][0] = nm0; m[qt][1] = nm1;
                float s0 = 0.f, s1 = 0.f;
#pragma unroll
                for (int t = 0; t < 4; t++) {
                    s[t][0] = tf32f(__expf(s[t][0] - nm0));
                    s[t][1] = tf32f(__expf(s[t][1] - nm0));
                    s[t][2] = tf32f(__expf(s[t][2] - nm1));
                    s[t][3] = tf32f(__expf(s[t][3] - nm1));
                    s0 += s[t][0] + s[t][1];
                    s1 += s[t][2] + s[t][3];
                }
                l[qt][0] = l[qt][0] * f0 + s0;
                l[qt][1] = l[qt][1] * f1 + s1;
#pragma unroll
                for (int n = 0; n < 2; n++) {
                    o[qt][n][0] *= f0; o[qt][n][1] *= f0;
                    o[qt][n][2] *= f1; o[qt][n][3] *= f1;
                }
#pragma unroll
                for (int t = 0; t < 4; t++) {
                    unsigned a[4];
                    {
                        const float t00 = __shfl_sync(0xffffffffu, s[t][0], src0);
                        const float t01 = __shfl_sync(0xffffffffu, s[t][1], src0);
                        const float t10 = __shfl_sync(0xffffffffu, s[t][2], src0);
                        const float t11 = __shfl_sync(0xffffffffu, s[t][3], src0);
                        a[0] = __float_as_uint((tg & 1) ? t01 : t00);
                        a[1] = __float_as_uint((tg & 1) ? t11 : t10);
                        const float u00 = __shfl_sync(0xffffffffu, s[t][0], src2);
                        const float u01 = __shfl_sync(0xffffffffu, s[t][1], src2);
                        const float u10 = __shfl_sync(0xffffffffu, s[t][2], src2);
                        const float u11 = __shfl_sync(0xffffffffu, s[t][3], src2);
                        a[2] = __float_as_uint((tg & 1) ? u01 : u00);
                        a[3] = __float_as_uint((tg & 1) ? u11 : u10);
                    }
                    const int key = sub * 32 + t * 8;
                    unsigned vb0[2], vb1[2];
                    vb0[0] = sV[key + tg][g];         vb0[1] = sV[key + tg + 4][g];
                    vb1[0] = sV[key + tg][g + 8];     vb1[1] = sV[key + tg + 4][g + 8];
                    mma_tf32(o[qt][0], a, vb0);
                    mma_tf32(o[qt][1], a, vb1);
                }
            }
        }
    }

#pragma unroll
    for (int qt = 0; qt < 3; qt++) {
        float l0 = l[qt][0], l1 = l[qt][1];
        l0 += __shfl_xor_sync(0xffffffffu, l0, 1);
        l0 += __shfl_xor_sync(0xffffffffu, l0, 2);
        l1 += __shfl_xor_sync(0xffffffffu, l1, 1);
        l1 += __shfl_xor_sync(0xffffffffu, l1, 2);
        const float inv0 = 1.f / l0, inv1 = 1.f / l1;
        const int row = qbase + qt * 16 + g;
        float* out0 = g_attn + ((size_t)b * KTOK + row) * CCH + h * 16 + tg * 2;
        float* out8 = out0 + 8 * CCH;
#pragma unroll
        for (int n = 0; n < 2; n++) {
            *(float2*)(out0 + n * 8) = make_float2(o[qt][n][0] * inv0, o[qt][n][1] * inv0);
            *(float2*)(out8 + n * 8) = make_float2(o[qt][n][2] * inv1, o[qt][n][3] * inv1);
        }
    }
}

// ---------------------------------------------------------------------------
// 8) residual + LayerNorm
// ---------------------------------------------------------------------------
__global__ void ln_kernel(const float* __restrict__ a, const float* __restrict__ r,
                          const float* __restrict__ g, const float* __restrict__ be,
                          float* __restrict__ out)
{
    const int row  = blockIdx.x * 8 + (threadIdx.x >> 5);
    const int lane = threadIdx.x & 31;
    const float4 va = ((const float4*)(a + (size_t)row * CCH))[lane];
    const float4 vr = ((const float4*)(r + (size_t)row * CCH))[lane];
    float4 t;
    t.x = va.x + vr.x; t.y = va.y + vr.y; t.z = va.z + vr.z; t.w = va.w + vr.w;
    float s  = t.x + t.y + t.z + t.w;
    float s2 = t.x*t.x + t.y*t.y + t.z*t.z + t.w*t.w;
#pragma unroll
    for (int o = 16; o > 0; o >>= 1) {
        s  += __shfl_xor_sync(0xffffffffu, s,  o);
        s2 += __shfl_xor_sync(0xffffffffu, s2, o);
    }
    const float mu  = s * (1.f / 128.f);
    const float var = s2 * (1.f / 128.f) - mu * mu;
    const float inv = rsqrtf(var + 1e-5f);
    const float4 gv = ((const float4*)g)[lane];
    const float4 bv = ((const float4*)be)[lane];
    float4 o;
    o.x = (t.x - mu) * inv * gv.x + bv.x;
    o.y = (t.y - mu) * inv * gv.y + bv.y;
    o.z = (t.z - mu) * inv * gv.z + bv.z;
    o.w = (t.w - mu) * inv * gv.w + bv.w;
    ((float4*)(out + (size_t)row * CCH))[lane] = o;
}

// ---------------------------------------------------------------------------
// 9) out = x * imp (everywhere), then scatter t2 at selected pixels
// ---------------------------------------------------------------------------
__global__ void xs_kernel(const float* __restrict__ x, float* __restrict__ out)
{
    const unsigned i = blockIdx.x * 256u + threadIdx.x;
    const unsigned total = (unsigned)BATCH * CCH * (PIX / 4);
    if (i >= total) return;
    const unsigned base = i * 4u;
    const unsigned p4 = base % PIX;
    const unsigned b  = (base / PIX) / CCH;
    const float4 xv = *(const float4*)(x + base);
    const float* ip = g_imp + (size_t)b * PIX + p4;
    float4 o;
    o.x = xv.x * ip[0]; o.y = xv.y * ip[1]; o.z = xv.z * ip[2]; o.w = xv.w * ip[3];
    *(float4*)(out + base) = o;
}

__global__ void scatter_kernel(float* __restrict__ out)
{
    const int b = blockIdx.y, k = blockIdx.x, c = threadIdx.x;
    const int p = g_idx[b * KTOK + k];
    out[((size_t)b * CCH + c) * PIX + p] = g_t2[((size_t)b * KTOK + k) * CCH + c];
}

// ---------------------------------------------------------------------------
// launch
// ---------------------------------------------------------------------------
extern "C" void kernel_launch(void* const* d_in, const int* in_sizes, int n_in,
                              void* d_out, int out_size)
{
    const float* x      = (const float*)d_in[0];
    const float* conv_w = (const float*)d_in[1];
    const float* conv_b = (const float*)d_in[2];
    const float* bn_g   = (const float*)d_in[3];
    const float* bn_b   = (const float*)d_in[4];
    const float* bn_m   = (const float*)d_in[5];
    const float* bn_v   = (const float*)d_in[6];
    const float* w_qkv  = (const float*)d_in[7];
    const float* b_qkv  = (const float*)d_in[8];
    const float* w_o    = (const float*)d_in[9];
    const float* b_o    = (const float*)d_in[10];
    const float* ln1_g  = (const float*)d_in[11];
    const float* ln1_b  = (const float*)d_in[12];
    const float* w1     = (const float*)d_in[13];
    const float* b1     = (const float*)d_in[14];
    const float* w2     = (const float*)d_in[15];
    const float* b2     = (const float*)d_in[16];
    const float* ln2_g  = (const float*)d_in[17];
    const float* ln2_b  = (const float*)d_in[18];
    float* out = (float*)d_out;

    float *p_tokens, *p_qkv, *p_attn, *p_t1, *p_h1, *p_tmp, *p_t2;
    cudaGetSymbolAddress((void**)&p_tokens, g_tokens);
    cudaGetSymbolAddress((void**)&p_qkv,    g_qkv);
    cudaGetSymbolAddress((void**)&p_attn,   g_attn);
    cudaGetSymbolAddress((void**)&p_t1,     g_t1);
    cudaGetSymbolAddress((void**)&p_h1,     g_h1);
    cudaGetSymbolAddress((void**)&p_tmp,    g_tmp);
    cudaGetSymbolAddress((void**)&p_t2,     g_t2);

    const int convgemm_smem = (2 * 64 * 132 + 2 * 32 * 132) * (int)sizeof(unsigned);
    cudaFuncSetAttribute(convgemm_kernel, cudaFuncAttributeMaxDynamicSharedMemorySize,
                         convgemm_smem);
    cudaFuncSetAttribute(topk_kernel, cudaFuncAttributeMaxDynamicSharedMemorySize,
                         PIX * (int)sizeof(unsigned));

    // conv (tensor-core GEMM + flat shift-add/activation) -> top-K -> tokens
    freq_kernel<<<1, 64>>>();
    convgemm_kernel<<<dim3(NPT, BATCH), 256, convgemm_smem>>>(x, conv_w);
    convadd_kernel<<<(BATCH * PIX + 255) / 256, 256>>>(conv_b, bn_g, bn_b, bn_m, bn_v);
    topk_kernel<<<BATCH, TKT, PIX * sizeof(unsigned)>>>();
    gather_kernel<<<dim3(KTOK, BATCH), CCH>>>(x);

    // transformer encoder layer (tf32 tensor cores throughout)
    gemm_tf32<false><<<dim3(384 / 64, NTOK / 128), 256>>>(p_tokens, w_qkv, b_qkv, p_qkv, NTOK, 384, 128);

    attn_kernel<<<dim3(NHEAD, BATCH, 2), 256>>>();

    gemm_tf32<false><<<dim3(128 / 64, NTOK / 128), 256>>>(p_attn, w_o, b_o, p_tmp, NTOK, 128, 128);
    ln_kernel<<<NTOK / 8, 256>>>(p_tokens, p_tmp, ln1_g, ln1_b, p_t1);
    gemm_tf32<true ><<<dim3(256 / 64, NTOK / 128), 256>>>(p_t1, w1, b1, p_h1, NTOK, 256, 128);
    gemm_tf32<false><<<dim3(128 / 64, NTOK / 128), 256>>>(p_h1, w2, b2, p_tmp, NTOK, 128, 256);
    ln_kernel<<<NTOK / 8, 256>>>(p_t1, p_tmp, ln2_g, ln2_b, p_t2);

    // assemble output
    xs_kernel<<<(BATCH * CCH * (PIX / 4) + 255) / 256, 256>>>(x, out);
    scatter_kernel<<<dim3(KTOK, BATCH), CCH>>>(out);
}

// round 8
// speedup vs baseline: 1.5114x; 1.0458x over previous
#include <cuda_runtime.h>
#include <cuda_bf16.h>
#include <math.h>

// ---------------------------------------------------------------------------
// Problem constants
// ---------------------------------------------------------------------------
#define BATCH 32
#define CCH   128           // channels / d_model
#define HH    110           // spatial
#define PIX   (HH*HH)       // 12100
#define KTOK  768
#define NHEAD 8
#define HD    16
#define NTOK  (BATCH*KTOK)  // 24576
#define YSTR  112           // padded row stride for y maps
#define CNT   128           // conv GEMM pixel tile
#define NPT   ((PIX + CNT - 1) / CNT)   // 95

typedef unsigned long long u64;

// ---------------------------------------------------------------------------
// helpers
// ---------------------------------------------------------------------------
__device__ __forceinline__ unsigned tf32_of(float x) {
    unsigned r; asm("cvt.rna.tf32.f32 %0, %1;" : "=r"(r) : "f"(x)); return r;
}
__device__ __forceinline__ float tf32f(float x) {
    return __uint_as_float(tf32_of(x));
}
__device__ __forceinline__ void split_tf32(float v, unsigned &hi, unsigned &lo) {
    hi = tf32_of(v);
    lo = tf32_of(v - __uint_as_float(hi));
}
__device__ __forceinline__ void mma_tf32(float* c, const unsigned* a, const unsigned* b) {
    asm("mma.sync.aligned.m16n8k8.row.col.f32.tf32.tf32.f32 "
        "{%0,%1,%2,%3},{%4,%5,%6,%7},{%8,%9},{%0,%1,%2,%3};"
        : "+f"(c[0]), "+f"(c[1]), "+f"(c[2]), "+f"(c[3])
        : "r"(a[0]), "r"(a[1]), "r"(a[2]), "r"(a[3]), "r"(b[0]), "r"(b[1]));
}

// ---------------------------------------------------------------------------
// Scratch (static device globals; no allocation allowed)
// ---------------------------------------------------------------------------
__device__ float g_yt[(size_t)BATCH*49*HH*YSTR];  // per-tap channel-reduced maps
__device__ float g_imp[BATCH*PIX];                // importance map
__device__ int   g_idx[BATCH*KTOK];               // selected pixel indices
__device__ int   g_inv[BATCH*PIX];                // pixel -> token slot (or -1)
__device__ float g_freq[64];                      // positional-encoding freqs
__device__ float g_tokens[NTOK*CCH];
__device__ float g_qkv[NTOK*3*CCH];
__device__ float g_attn[NTOK*CCH];
__device__ float g_t1[NTOK*CCH];
__device__ float g_h1[NTOK*2*CCH];
__device__ float g_t2[NTOK*CCH];

// ---------------------------------------------------------------------------
// 1a) conv as GEMM (3xTF32, fp32-accurate): Y[t][p] = sum_c W[t][c] X[c][p].
// ---------------------------------------------------------------------------
__global__ __launch_bounds__(256) void convgemm_kernel(
    const float* __restrict__ x, const float* __restrict__ w)
{
    extern __shared__ unsigned csm[];
    unsigned (*Ah)[132] = (unsigned(*)[132])csm;            // 64 x 132
    unsigned (*Al)[132] = Ah + 64;
    unsigned (*Bh)[132] = Al + 64;                          // 32 x 132
    unsigned (*Bl)[132] = Bh + 32;

    const int pt = blockIdx.x, b = blockIdx.y;
    const int p0 = pt * CNT;
    const int tid = threadIdx.x, lane = tid & 31, wid = tid >> 5;
    const int wm = wid >> 2, wn = wid & 3;
    const int g = lane >> 2, tg = lane & 3;

    for (int e = tid; e < 64 * 128; e += 256) {
        const int t = e & 63, c = e >> 6;
        const float v = (t < 49) ? w[c * 49 + t] : 0.f;
        split_tf32(v, Ah[t][c], Al[t][c]);
    }

    float acc[2][4][4];
#pragma unroll
    for (int mi = 0; mi < 2; mi++)
#pragma unroll
        for (int ni = 0; ni < 4; ni++)
#pragma unroll
            for (int e = 0; e < 4; e++) acc[mi][ni][e] = 0.f;

    for (int k0 = 0; k0 < 128; k0 += 32) {
        __syncthreads();
        for (int e = tid; e < 32 * 128; e += 256) {
            const int c = e >> 7, p = e & 127;
            const int gp = p0 + p;
            const float v = (gp < PIX) ? x[((size_t)b * CCH + k0 + c) * PIX + gp] : 0.f;
            split_tf32(v, Bh[c][p], Bl[c][p]);
        }
        __syncthreads();
#pragma unroll
        for (int ks = 0; ks < 4; ks++) {
            const int kk = k0 + ks * 8 + tg;
            const int kb = ks * 8 + tg;
            unsigned ah[2][4], al[2][4];
#pragma unroll
            for (int mi = 0; mi < 2; mi++) {
                const int rr = wm * 32 + mi * 16 + g;
                ah[mi][0] = Ah[rr][kk];      al[mi][0] = Al[rr][kk];
                ah[mi][1] = Ah[rr + 8][kk];  al[mi][1] = Al[rr + 8][kk];
                ah[mi][2] = Ah[rr][kk + 4];  al[mi][2] = Al[rr][kk + 4];
                ah[mi][3] = Ah[rr + 8][kk+4];al[mi][3] = Al[rr + 8][kk+4];
            }
#pragma unroll
            for (int ni = 0; ni < 4; ni++) {
                const int n0 = wn * 32 + ni * 8 + g;
                unsigned bh[2], bl[2];
                bh[0] = Bh[kb][n0];     bl[0] = Bl[kb][n0];
                bh[1] = Bh[kb + 4][n0]; bl[1] = Bl[kb + 4][n0];
#pragma unroll
                for (int mi = 0; mi < 2; mi++) {
                    mma_tf32(acc[mi][ni], ah[mi], bh);
                    mma_tf32(acc[mi][ni], al[mi], bh);
                    mma_tf32(acc[mi][ni], ah[mi], bl);
                }
            }
        }
    }

#pragma unroll
    for (int mi = 0; mi < 2; mi++) {
        const int t = wm * 32 + mi * 16 + g;
#pragma unroll
        for (int ni = 0; ni < 4; ni++) {
            const int pcol = p0 + wn * 32 + ni * 8 + tg * 2;
            if (pcol < PIX) {
                const int r0r = pcol / HH, c0r = pcol - r0r * HH;
                const bool ok1 = (pcol + 1 < PIX);
                const int r1r = (pcol + 1) / HH, c1r = (pcol + 1) - r1r * HH;
                if (t < 49) {
                    float* yb = g_yt + ((size_t)b * 49 + t) * HH * YSTR;
                    yb[r0r * YSTR + c0r] = acc[mi][ni][0];
                    if (ok1) yb[r1r * YSTR + c1r] = acc[mi][ni][1];
                }
                if (t + 8 < 49) {
                    float* yb = g_yt + ((size_t)b * 49 + t + 8) * HH * YSTR;
                    yb[r0r * YSTR + c0r] = acc[mi][ni][2];
                    if (ok1) yb[r1r * YSTR + c1r] = acc[mi][ni][3];
                }
            }
        }
    }
}

// ---------------------------------------------------------------------------
// 1b) shift-add over 49 taps + BN + GELU + sigmoid, one thread per pixel.
// ---------------------------------------------------------------------------
__global__ void convadd_kernel(
    const float* __restrict__ cb, const float* __restrict__ bg,
    const float* __restrict__ bb, const float* __restrict__ bm,
    const float* __restrict__ bv)
{
    const int idx = blockIdx.x * 256 + threadIdx.x;
    if (idx >= BATCH * PIX) return;
    const int b = idx / PIX, p = idx - b * PIX;
    const int r = p / HH, c = p - r * HH;
    const float* yb = g_yt + (size_t)b * 49 * HH * YSTR;

    float a = 0.f;
#pragma unroll
    for (int u = 0; u < 7; u++) {
        const int sr = r + 5 * (u - 3);
        if (sr < 0 || sr >= HH) continue;
#pragma unroll
        for (int v = 0; v < 7; v++) {
            const int sc = c + 5 * (v - 3);
            if (sc >= 0 && sc < HH)
                a += yb[((u * 7 + v) * HH + sr) * YSTR + sc];
        }
    }

    const float scale = bg[0] * rsqrtf(bv[0] + 1e-5f);
    float y = a + cb[0];
    y = (y - bm[0]) * scale + bb[0];
    const float gl = 0.5f * y * (1.f + erff(y * 0.70710678118654752f));
    g_imp[idx] = 1.f / (1.f + expf(-gl));
}

// ---------------------------------------------------------------------------
// 3) top-K per batch: radix-256 threshold + ballot compaction. Also fills
//    the inverse map g_inv (pixel -> token slot, -1 elsewhere).
// ---------------------------------------------------------------------------
#define NCHK ((PIX + 255) / 256)   // 48
#define TKT  1024

__global__ __launch_bounds__(TKT) void topk_kernel()
{
    extern __shared__ unsigned sbits[];     // [PIX]
    __shared__ int hist[256];
    __shared__ int cgt[NCHK], ceq[NCHK];
    __shared__ unsigned sh_prefix;
    __shared__ int sh_above;

    const int b    = blockIdx.x;
    const int tid  = threadIdx.x;
    const int lane = tid & 31;
    const int wrp  = tid >> 5;              // 0..31
    const float* v = g_imp + b * PIX;

    for (int i = tid; i < PIX; i += TKT) {
        sbits[i] = __float_as_uint(v[i]);
        g_inv[b * PIX + i] = -1;
    }
    __syncthreads();

    unsigned prefix = 0;
    int kneed = KTOK;

#pragma unroll
    for (int shift = 24; shift >= 0; shift -= 8) {
        if (tid < 256) hist[tid] = 0;
        __syncthreads();
        const unsigned pm = (shift == 24) ? 0u : (0xFFFFFFFFu << (shift + 8));
        for (int i = tid; i < PIX; i += TKT) {
            const unsigned bits = sbits[i];
            if ((bits & pm) == prefix)
                atomicAdd(&hist[(bits >> shift) & 255], 1);
        }
        __syncthreads();
        for (int off = 1; off < 256; off <<= 1) {
            int val = 0;
            if (tid < 256) val = (tid + off < 256) ? hist[tid + off] : 0;
            __syncthreads();
            if (tid < 256) hist[tid] += val;
            __syncthreads();
        }
        if (tid < 256) {
            const int here  = hist[tid];
            const int above = (tid == 255) ? 0 : hist[tid + 1];
            if (here >= kneed && above < kneed) {
                sh_prefix = prefix | ((unsigned)tid << shift);
                sh_above  = above;
            }
        }
        __syncthreads();
        prefix = sh_prefix;
        kneed -= sh_above;
        __syncthreads();
    }

    const unsigned T = prefix;
    const int tn = kneed;                    // ties to take (lowest index first)

    for (int c = wrp; c < NCHK; c += 32) {
        int gt = 0, eq = 0;
#pragma unroll
        for (int g = 0; g < 8; g++) {
            const int i = c * 256 + g * 32 + lane;
            const unsigned bits = (i < PIX) ? sbits[i] : 0u;
            const unsigned bg = __ballot_sync(0xffffffffu, bits > T);
            const unsigned be = __ballot_sync(0xffffffffu, bits == T && i < PIX);
            gt += __popc(bg); eq += __popc(be);
        }
        if (lane == 0) { cgt[c] = gt; ceq[c] = eq; }
    }
    __syncthreads();
    if (tid == 0) {
        int sg = 0, se = 0;
        for (int c = 0; c < NCHK; c++) {
            const int tg2 = cgt[c], te = ceq[c];
            cgt[c] = sg; ceq[c] = se;
            sg += tg2; se += te;
        }
    }
    __syncthreads();

    const unsigned lmask = (1u << lane) - 1u;
    for (int c = wrp; c < NCHK; c += 32) {
        int gt_run = cgt[c], eq_run = ceq[c];
#pragma unroll
        for (int g = 0; g < 8; g++) {
            const int i = c * 256 + g * 32 + lane;
            const unsigned bits = (i < PIX) ? sbits[i] : 0u;
            const bool isgt = bits > T;
            const bool iseq = (bits == T) && (i < PIX);
            const unsigned bg = __ballot_sync(0xffffffffu, isgt);
            const unsigned be = __ballot_sync(0xffffffffu, iseq);
            const int gt_before = gt_run + __popc(bg & lmask);
            const int eq_before = eq_run + __popc(be & lmask);
            int slot = -1;
            if (isgt)                         slot = gt_before + min(eq_before, tn);
            else if (iseq && eq_before < tn)  slot = gt_before + eq_before;
            if (slot >= 0) {
                g_idx[b * KTOK + slot] = i;
                g_inv[b * PIX + i] = slot;
            }
            gt_run += __popc(bg);
            eq_run += __popc(be);
        }
    }
}

// ---------------------------------------------------------------------------
// 4) positional-encoding frequency table
// ---------------------------------------------------------------------------
__global__ void freq_kernel()
{
    const int i = threadIdx.x;           // 64
    const float cst = (float)(-(log(10000.0) / 128.0));
    const float a = (float)(2 * i) * cst;
    g_freq[i] = (float)exp((double)a);
}

// ---------------------------------------------------------------------------
// 5) gather tokens: tokens[b,k,c] = x[b,c,p]*imp[b,p] + PE[p,c]
// ---------------------------------------------------------------------------
__global__ void gather_kernel(const float* __restrict__ x)
{
    const int b = blockIdx.y, k = blockIdx.x, c = threadIdx.x;
    const int p = g_idx[b * KTOK + k];
    const float val = x[((size_t)b * CCH + c) * PIX + p] * g_imp[b * PIX + p];
    const float arg = (float)p * g_freq[c >> 1];
    const float pe  = (c & 1) ? cosf(arg) : sinf(arg);
    g_tokens[((size_t)b * KTOK + k) * CCH + c] = val + pe;
}

// ---------------------------------------------------------------------------
// 6) tf32 tensor-core GEMM: C[m,n] = act( sum_k A[m,k]*B[n,k] + bias[n] )
//    BM=128, BN=64 — used for qkv and ffn1.
// ---------------------------------------------------------------------------
template <bool RELU>
__global__ __launch_bounds__(256) void gemm_tf32(
    const float* __restrict__ A, const float* __restrict__ B,
    const float* __restrict__ bias, float* __restrict__ C,
    int M, int N, int K)
{
    __shared__ unsigned As[128][33];
    __shared__ unsigned Bs[64][33];

    const int tid  = threadIdx.x;
    const int lane = tid & 31;
    const int wid  = tid >> 5;
    const int wm   = wid >> 1;
    const int wn   = wid & 1;
    const int g    = lane >> 2;
    const int tg   = lane & 3;
    const int bm   = blockIdx.y * 128, bn = blockIdx.x * 64;

    float acc[2][4][4];
#pragma unroll
    for (int mi = 0; mi < 2; mi++)
#pragma unroll
        for (int ni = 0; ni < 4; ni++)
#pragma unroll
            for (int e = 0; e < 4; e++) acc[mi][ni][e] = 0.f;

    for (int k0 = 0; k0 < K; k0 += 32) {
#pragma unroll
        for (int i = 0; i < 4; i++) {
            const int f = tid + i * 256;
            const int row = f >> 3, c4 = (f & 7) * 4;
            const float4 v = *(const float4*)&A[(size_t)(bm + row) * K + k0 + c4];
            As[row][c4 + 0] = tf32_of(v.x); As[row][c4 + 1] = tf32_of(v.y);
            As[row][c4 + 2] = tf32_of(v.z); As[row][c4 + 3] = tf32_of(v.w);
        }
#pragma unroll
        for (int i = 0; i < 2; i++) {
            const int f = tid + i * 256;
            const int row = f >> 3, c4 = (f & 7) * 4;
            const float4 v = *(const float4*)&B[(size_t)(bn + row) * K + k0 + c4];
            Bs[row][c4 + 0] = tf32_of(v.x); Bs[row][c4 + 1] = tf32_of(v.y);
            Bs[row][c4 + 2] = tf32_of(v.z); Bs[row][c4 + 3] = tf32_of(v.w);
        }
        __syncthreads();

#pragma unroll
        for (int ks = 0; ks < 4; ks++) {
            const int kb = ks * 8;
            unsigned a[2][4], bf[4][2];
#pragma unroll
            for (int mi = 0; mi < 2; mi++) {
                const int r0 = wm * 32 + mi * 16 + g;
                a[mi][0] = As[r0][kb + tg];
                a[mi][1] = As[r0 + 8][kb + tg];
                a[mi][2] = As[r0][kb + tg + 4];
                a[mi][3] = As[r0 + 8][kb + tg + 4];
            }
#pragma unroll
            for (int ni = 0; ni < 4; ni++) {
                const int n0 = wn * 32 + ni * 8 + g;
                bf[ni][0] = Bs[n0][kb + tg];
                bf[ni][1] = Bs[n0][kb + tg + 4];
            }
#pragma unroll
            for (int mi = 0; mi < 2; mi++)
#pragma unroll
                for (int ni = 0; ni < 4; ni++)
                    mma_tf32(acc[mi][ni], a[mi], bf[ni]);
        }
        __syncthreads();
    }

#pragma unroll
    for (int mi = 0; mi < 2; mi++) {
        const int r0 = bm + wm * 32 + mi * 16 + g;
#pragma unroll
        for (int ni = 0; ni < 4; ni++) {
            const int c0 = bn + wn * 32 + ni * 8 + tg * 2;
            const float b0 = bias[c0], b1 = bias[c0 + 1];
            float2 v0 = { acc[mi][ni][0] + b0, acc[mi][ni][1] + b1 };
            float2 v1 = { acc[mi][ni][2] + b0, acc[mi][ni][3] + b1 };
            if (RELU) {
                v0.x = fmaxf(v0.x, 0.f); v0.y = fmaxf(v0.y, 0.f);
                v1.x = fmaxf(v1.x, 0.f); v1.y = fmaxf(v1.y, 0.f);
            }
            *(float2*)&C[(size_t)r0 * N + c0]       = v0;
            *(float2*)&C[(size_t)(r0 + 8) * N + c0] = v1;
        }
    }
}

// ---------------------------------------------------------------------------
// 6b) fused GEMM + bias + residual + LayerNorm. BN = 128 = full d_model.
//     out[m][:] = LN( A@B^T + bias + R[m][:] ) * gamma + beta
//     256 threads = 8 warps (4m x 2n). Used for o-proj+LN1 and ffn2+LN2.
// ---------------------------------------------------------------------------
__global__ __launch_bounds__(256) void gemm_ln(
    const float* __restrict__ A, const float* __restrict__ B,
    const float* __restrict__ bias, const float* __restrict__ R,
    const float* __restrict__ gam, const float* __restrict__ bet,
    float* __restrict__ out, int K)
{
    __shared__ unsigned As[128][33];
    __shared__ unsigned Bs[128][33];
    __shared__ float2 part[2][128];      // per-half (sum, sumsq) per row

    const int tid  = threadIdx.x;
    const int lane = tid & 31;
    const int wid  = tid >> 5;
    const int wm   = wid >> 1;           // 0..3
    const int wn   = wid & 1;            // 0..1 (64-col halves)
    const int g    = lane >> 2;
    const int tg   = lane & 3;
    const int bm   = blockIdx.x * 128;

    float acc[2][8][4];
#pragma unroll
    for (int mi = 0; mi < 2; mi++)
#pragma unroll
        for (int ni = 0; ni < 8; ni++)
#pragma unroll
            for (int e = 0; e < 4; e++) acc[mi][ni][e] = 0.f;

    for (int k0 = 0; k0 < K; k0 += 32) {
#pragma unroll
        for (int i = 0; i < 4; i++) {
            const int f = tid + i * 256;
            const int row = f >> 3, c4 = (f & 7) * 4;
            const float4 va = *(const float4*)&A[(size_t)(bm + row) * K + k0 + c4];
            As[row][c4 + 0] = tf32_of(va.x); As[row][c4 + 1] = tf32_of(va.y);
            As[row][c4 + 2] = tf32_of(va.z); As[row][c4 + 3] = tf32_of(va.w);
            const float4 vb = *(const float4*)&B[(size_t)row * K + k0 + c4];
            Bs[row][c4 + 0] = tf32_of(vb.x); Bs[row][c4 + 1] = tf32_of(vb.y);
            Bs[row][c4 + 2] = tf32_of(vb.z); Bs[row][c4 + 3] = tf32_of(vb.w);
        }
        __syncthreads();

#pragma unroll
        for (int ks = 0; ks < 4; ks++) {
            const int kb = ks * 8;
            unsigned a[2][4], bf[8][2];
#pragma unroll
            for (int mi = 0; mi < 2; mi++) {
                const int r0 = wm * 32 + mi * 16 + g;
                a[mi][0] = As[r0][kb + tg];
                a[mi][1] = As[r0 + 8][kb + tg];
                a[mi][2] = As[r0][kb + tg + 4];
                a[mi][3] = As[r0 + 8][kb + tg + 4];
            }
#pragma unroll
            for (int ni = 0; ni < 8; ni++) {
                const int n0 = wn * 64 + ni * 8 + g;
                bf[ni][0] = Bs[n0][kb + tg];
                bf[ni][1] = Bs[n0][kb + tg + 4];
            }
#pragma unroll
            for (int mi = 0; mi < 2; mi++)
#pragma unroll
                for (int ni = 0; ni < 8; ni++)
                    mma_tf32(acc[mi][ni], a[mi], bf[ni]);
        }
        __syncthreads();
    }

    // bias + residual, per-row partial stats
    float v0s[2][8][2], v1s[2][8][2];    // values for rows r, r+8
    float sum[2][2], sq[2][2];           // [mi][row-half]
#pragma unroll
    for (int mi = 0; mi < 2; mi++) {
        sum[mi][0] = sum[mi][1] = 0.f;
        sq[mi][0]  = sq[mi][1]  = 0.f;
        const int r0 = bm + wm * 32 + mi * 16 + g;
#pragma unroll
        for (int ni = 0; ni < 8; ni++) {
            const int c0 = wn * 64 + ni * 8 + tg * 2;
            const float b0 = bias[c0], b1 = bias[c0 + 1];
            const float2 ra = *(const float2*)&R[(size_t)r0 * CCH + c0];
            const float2 rb = *(const float2*)&R[(size_t)(r0 + 8) * CCH + c0];
            const float x0 = acc[mi][ni][0] + b0 + ra.x;
            const float x1 = acc[mi][ni][1] + b1 + ra.y;
            const float x2 = acc[mi][ni][2] + b0 + rb.x;
            const float x3 = acc[mi][ni][3] + b1 + rb.y;
            v0s[mi][ni][0] = x0; v0s[mi][ni][1] = x1;
            v1s[mi][ni][0] = x2; v1s[mi][ni][1] = x3;
            sum[mi][0] += x0 + x1;         sq[mi][0] += x0*x0 + x1*x1;
            sum[mi][1] += x2 + x3;         sq[mi][1] += x2*x2 + x3*x3;
        }
        // quad reduce (tg lanes)
#pragma unroll
        for (int off = 1; off < 4; off <<= 1) {
            sum[mi][0] += __shfl_xor_sync(0xffffffffu, sum[mi][0], off);
            sq[mi][0]  += __shfl_xor_sync(0xffffffffu, sq[mi][0],  off);
            sum[mi][1] += __shfl_xor_sync(0xffffffffu, sum[mi][1], off);
            sq[mi][1]  += __shfl_xor_sync(0xffffffffu, sq[mi][1],  off);
        }
    }
    if (tg == 0) {
#pragma unroll
        for (int mi = 0; mi < 2; mi++) {
            const int rl = wm * 32 + mi * 16 + g;
            part[wn][rl]     = make_float2(sum[mi][0], sq[mi][0]);
            part[wn][rl + 8] = make_float2(sum[mi][1], sq[mi][1]);
        }
    }
    __syncthreads();

#pragma unroll
    for (int mi = 0; mi < 2; mi++) {
        const int rl = wm * 32 + mi * 16 + g;
#pragma unroll
        for (int half = 0; half < 2; half++) {
            const float2 p0 = part[0][rl + half * 8];
            const float2 p1 = part[1][rl + half * 8];
            const float mu  = (p0.x + p1.x) * (1.f / 128.f);
            const float var = (p0.y + p1.y) * (1.f / 128.f) - mu * mu;
            const float inv = rsqrtf(var + 1e-5f);
            const int row = bm + wm * 32 + mi * 16 + half * 8 + g;
#pragma unroll
            for (int ni = 0; ni < 8; ni++) {
                const int c0 = wn * 64 + ni * 8 + tg * 2;
                const float gv0 = gam[c0], gv1 = gam[c0 + 1];
                const float bv0 = bet[c0], bv1 = bet[c0 + 1];
                const float x0 = (half == 0) ? v0s[mi][ni][0] : v1s[mi][ni][0];
                const float x1 = (half == 0) ? v0s[mi][ni][1] : v1s[mi][ni][1];
                float2 o;
                o.x = (x0 - mu) * inv * gv0 + bv0;
                o.y = (x1 - mu) * inv * gv1 + bv1;
                *(float2*)&out[(size_t)row * CCH + c0] = o;
            }
        }
    }
}

// ---------------------------------------------------------------------------
// 7) tensor-core flash attention. grid (NHEAD, BATCH, 2), 256 threads.
// ---------------------------------------------------------------------------
__global__ __launch_bounds__(256) void attn_kernel()
{
    __shared__ unsigned sK[256][18];
    __shared__ unsigned sV[256][24];

    const int h = blockIdx.x, b = blockIdx.y, qh = blockIdx.z;
    const int tid  = threadIdx.x;
    const int lane = tid & 31;
    const int w    = tid >> 5;
    const int g    = lane >> 2;
    const int tg   = lane & 3;
    const float* qkv = g_qkv + (size_t)b * KTOK * 384;
    const int qbase = qh * 384 + w * 48;

    unsigned qa[3][8];
#pragma unroll
    for (int qt = 0; qt < 3; qt++) {
        const int row = qbase + qt * 16 + g;
        const float* q0 = qkv + (size_t)row * 384 + h * 16;
        const float* q8 = q0 + 8 * 384;
        qa[qt][0] = tf32_of(q0[tg]      * 0.25f);
        qa[qt][1] = tf32_of(q8[tg]      * 0.25f);
        qa[qt][2] = tf32_of(q0[tg + 4]  * 0.25f);
        qa[qt][3] = tf32_of(q8[tg + 4]  * 0.25f);
        qa[qt][4] = tf32_of(q0[tg + 8]  * 0.25f);
        qa[qt][5] = tf32_of(q8[tg + 8]  * 0.25f);
        qa[qt][6] = tf32_of(q0[tg + 12] * 0.25f);
        qa[qt][7] = tf32_of(q8[tg + 12] * 0.25f);
    }

    float m[3][2], l[3][2], o[3][2][4];
#pragma unroll
    for (int qt = 0; qt < 3; qt++) {
        m[qt][0] = m[qt][1] = -1e30f;
        l[qt][0] = l[qt][1] = 0.f;
#pragma unroll
        for (int n = 0; n < 2; n++)
#pragma unroll
            for (int e = 0; e < 4; e++) o[qt][n][e] = 0.f;
    }

    const int src0 = (lane & 28) | (tg >> 1);
    const int src2 = src0 + 2;

    for (int ch = 0; ch < 3; ch++) {
        __syncthreads();
        for (int e = tid; e < 256 * 16; e += 256) {
            const int j = e >> 4, d = e & 15;
            const size_t base = (size_t)(ch * 256 + j) * 384 + h * 16 + d;
            sK[j][d] = tf32_of(qkv[base + 128]);
            sV[j][d] = tf32_of(qkv[base + 256]);
        }
        __syncthreads();

        for (int sub = 0; sub < 8; sub++) {
            unsigned kb[4][2][2];
#pragma unroll
            for (int t = 0; t < 4; t++) {
                const int key = sub * 32 + t * 8 + g;
                kb[t][0][0] = sK[key][tg];
                kb[t][0][1] = sK[key][tg + 4];
                kb[t][1][0] = sK[key][tg + 8];
                kb[t][1][1] = sK[key][tg + 12];
            }
#pragma unroll
            for (int qt = 0; qt < 3; qt++) {
                float s[4][4];
#pragma unroll
                for (int t = 0; t < 4; t++) {
                    s[t][0] = s[t][1] = s[t][2] = s[t][3] = 0.f;
                    mma_tf32(s[t], qa[qt],     kb[t][0]);
                    mma_tf32(s[t], qa[qt] + 4, kb[t][1]);
                }
                float mx0 = s[0][0], mx1 = s[0][2];
#pragma unroll
                for (int t = 0; t < 4; t++) {
                    mx0 = fmaxf(mx0, fmaxf(s[t][0], s[t][1]));
                    mx1 = fmaxf(mx1, fmaxf(s[t][2], s[t][3]));
                }
                mx0 = fmaxf(mx0, __shfl_xor_sync(0xffffffffu, mx0, 1));
                mx0 = fmaxf(mx0, __shfl_xor_sync(0xffffffffu, mx0, 2));
                mx1 = fmaxf(mx1, __shfl_xor_sync(0xffffffffu, mx1, 1));
                mx1 = fmaxf(mx1, __shfl_xor_sync(0xffffffffu, mx1, 2));
                const float nm0 = fmaxf(m[qt][0], mx0);
                const float nm1 = fmaxf(m[qt][1], mx1);
                const float f0 = __expf(m[qt][0] - nm0);
                const float f1 = __expf(m[qt][1] - nm1);
                m[qt][0] = nm0; m[qt][1] = nm1;
                float s0 = 0.f, s1 = 0.f;
#pragma unroll
                for (int t = 0; t < 4; t++) {
                    s[t][0] = tf32f(__expf(s[t][0] - nm0));
                    s[t][1] = tf32f(__expf(s[t][1] - nm0));
                    s[t][2] = tf32f(__expf(s[t][2] - nm1));
                    s[t][3] = tf32f(__expf(s[t][3] - nm1));
                    s0 += s[t][0] + s[t][1];
                    s1 += s[t][2] + s[t][3];
                }
                l[qt][0] = l[qt][0] * f0 + s0;
                l[qt][1] = l[qt][1] * f1 + s1;
#pragma unroll
                for (int n = 0; n < 2; n++) {
                    o[qt][n][0] *= f0; o[qt][n][1] *= f0;
                    o[qt][n][2] *= f1; o[qt][n][3] *= f1;
                }
#pragma unroll
                for (int t = 0; t < 4; t++) {
                    unsigned a[4];
                    {
                        const float t00 = __shfl_sync(0xffffffffu, s[t][0], src0);
                        const float t01 = __shfl_sync(0xffffffffu, s[t][1], src0);
                        const float t10 = __shfl_sync(0xffffffffu, s[t][2], src0);
                        const float t11 = __shfl_sync(0xffffffffu, s[t][3], src0);
                        a[0] = __float_as_uint((tg & 1) ? t01 : t00);
                        a[1] = __float_as_uint((tg & 1) ? t11 : t10);
                        const float u00 = __shfl_sync(0xffffffffu, s[t][0], src2);
                        const float u01 = __shfl_sync(0xffffffffu, s[t][1], src2);
                        const float u10 = __shfl_sync(0xffffffffu, s[t][2], src2);
                        const float u11 = __shfl_sync(0xffffffffu, s[t][3], src2);
                        a[2] = __float_as_uint((tg & 1) ? u01 : u00);
                        a[3] = __float_as_uint((tg & 1) ? u11 : u10);
                    }
                    const int key = sub * 32 + t * 8;
                    unsigned vb0[2], vb1[2];
                    vb0[0] = sV[key + tg][g];         vb0[1] = sV[key + tg + 4][g];
                    vb1[0] = sV[key + tg][g + 8];     vb1[1] = sV[key + tg + 4][g + 8];
                    mma_tf32(o[qt][0], a, vb0);
                    mma_tf32(o[qt][1], a, vb1);
                }
            }
        }
    }

#pragma unroll
    for (int qt = 0; qt < 3; qt++) {
        float l0 = l[qt][0], l1 = l[qt][1];
        l0 += __shfl_xor_sync(0xffffffffu, l0, 1);
        l0 += __shfl_xor_sync(0xffffffffu, l0, 2);
        l1 += __shfl_xor_sync(0xffffffffu, l1, 1);
        l1 += __shfl_xor_sync(0xffffffffu, l1, 2);
        const float inv0 = 1.f / l0, inv1 = 1.f / l1;
        const int row = qbase + qt * 16 + g;
        float* out0 = g_attn + ((size_t)b * KTOK + row) * CCH + h * 16 + tg * 2;
        float* out8 = out0 + 8 * CCH;
#pragma unroll
        for (int n = 0; n < 2; n++) {
            *(float2*)(out0 + n * 8) = make_float2(o[qt][n][0] * inv0, o[qt][n][1] * inv0);
            *(float2*)(out8 + n * 8) = make_float2(o[qt][n][2] * inv1, o[qt][n][3] * inv1);
        }
    }
}

// ---------------------------------------------------------------------------
// 9) finalize: out = x*imp everywhere, except selected pixels take t2.
// ---------------------------------------------------------------------------
__global__ void finalize_kernel(const float* __restrict__ x, float* __restrict__ out)
{
    const unsigned i = blockIdx.x * 256u + threadIdx.x;
    const unsigned total = (unsigned)BATCH * CCH * (PIX / 4);
    if (i >= total) return;
    const unsigned base = i * 4u;
    const unsigned p4 = base % PIX;
    const unsigned bc = base / PIX;
    const unsigned b  = bc / CCH;
    const unsigned c  = bc - b * CCH;
    const float4 xv = *(const float4*)(x + base);
    const float* ip = g_imp + (size_t)b * PIX + p4;
    const int4  iv = *(const int4*)(g_inv + (size_t)b * PIX + p4);
    float4 o;
    o.x = (iv.x >= 0) ? g_t2[((size_t)b * KTOK + iv.x) * CCH + c] : xv.x * ip[0];
    o.y = (iv.y >= 0) ? g_t2[((size_t)b * KTOK + iv.y) * CCH + c] : xv.y * ip[1];
    o.z = (iv.z >= 0) ? g_t2[((size_t)b * KTOK + iv.z) * CCH + c] : xv.z * ip[2];
    o.w = (iv.w >= 0) ? g_t2[((size_t)b * KTOK + iv.w) * CCH + c] : xv.w * ip[3];
    *(float4*)(out + base) = o;
}

// ---------------------------------------------------------------------------
// launch
// ---------------------------------------------------------------------------
extern "C" void kernel_launch(void* const* d_in, const int* in_sizes, int n_in,
                              void* d_out, int out_size)
{
    const float* x      = (const float*)d_in[0];
    const float* conv_w = (const float*)d_in[1];
    const float* conv_b = (const float*)d_in[2];
    const float* bn_g   = (const float*)d_in[3];
    const float* bn_b   = (const float*)d_in[4];
    const float* bn_m   = (const float*)d_in[5];
    const float* bn_v   = (const float*)d_in[6];
    const float* w_qkv  = (const float*)d_in[7];
    const float* b_qkv  = (const float*)d_in[8];
    const float* w_o    = (const float*)d_in[9];
    const float* b_o    = (const float*)d_in[10];
    const float* ln1_g  = (const float*)d_in[11];
    const float* ln1_b  = (const float*)d_in[12];
    const float* w1     = (const float*)d_in[13];
    const float* b1     = (const float*)d_in[14];
    const float* w2     = (const float*)d_in[15];
    const float* b2     = (const float*)d_in[16];
    const float* ln2_g  = (const float*)d_in[17];
    const float* ln2_b  = (const float*)d_in[18];
    float* out = (float*)d_out;

    float *p_tokens, *p_qkv, *p_attn, *p_t1, *p_h1, *p_t2;
    cudaGetSymbolAddress((void**)&p_tokens, g_tokens);
    cudaGetSymbolAddress((void**)&p_qkv,    g_qkv);
    cudaGetSymbolAddress((void**)&p_attn,   g_attn);
    cudaGetSymbolAddress((void**)&p_t1,     g_t1);
    cudaGetSymbolAddress((void**)&p_h1,     g_h1);
    cudaGetSymbolAddress((void**)&p_t2,     g_t2);

    const int convgemm_smem = (2 * 64 * 132 + 2 * 32 * 132) * (int)sizeof(unsigned);
    cudaFuncSetAttribute(convgemm_kernel, cudaFuncAttributeMaxDynamicSharedMemorySize,
                         convgemm_smem);
    cudaFuncSetAttribute(topk_kernel, cudaFuncAttributeMaxDynamicSharedMemorySize,
                         PIX * (int)sizeof(unsigned));

    // conv -> importance -> top-K (+inverse map) -> tokens
    freq_kernel<<<1, 64>>>();
    convgemm_kernel<<<dim3(NPT, BATCH), 256, convgemm_smem>>>(x, conv_w);
    convadd_kernel<<<(BATCH * PIX + 255) / 256, 256>>>(conv_b, bn_g, bn_b, bn_m, bn_v);
    topk_kernel<<<BATCH, TKT, PIX * sizeof(unsigned)>>>();
    gather_kernel<<<dim3(KTOK, BATCH), CCH>>>(x);

    // transformer encoder layer (tf32 tensor cores, LN fused into GEMMs)
    gemm_tf32<false><<<dim3(384 / 64, NTOK / 128), 256>>>(p_tokens, w_qkv, b_qkv, p_qkv, NTOK, 384, 128);
    attn_kernel<<<dim3(NHEAD, BATCH, 2), 256>>>();
    gemm_ln<<<NTOK / 128, 256>>>(p_attn, w_o, b_o, p_tokens, ln1_g, ln1_b, p_t1, 128);
    gemm_tf32<true ><<<dim3(256 / 64, NTOK / 128), 256>>>(p_t1, w1, b1, p_h1, NTOK, 256, 128);
    gemm_ln<<<NTOK / 128, 256>>>(p_h1, w2, b2, p_t1, ln2_g, ln2_b, p_t2, 256);

    // assemble output in one pass
    finalize_kernel<<<(BATCH * CCH * (PIX / 4) + 255) / 256, 256>>>(x, out);
}